// round 1
// baseline (speedup 1.0000x reference)
#include <cuda_runtime.h>

// ---------------- problem constants ----------------
#define NHEAD 8
#define HD 32
#define NTOK 256
#define BATCH 256
#define DIMC 256
#define NGROUP 64
#define PD 16
#define LREL 961   // (2*16-1)^2

// ---------------- device scratch ----------------
__device__ float g_qh[BATCH * NTOK * DIMC];        // [b*256+n][c], c = h*32+d
__device__ float g_kv[BATCH * NTOK * 2 * DIMC];    // [b*256+n][c], k: c=h*32+d, v: c=256+h*32+d
__device__ float g_x [BATCH * NTOK * DIMC];        // attention output
__device__ float g_pos[LREL * NHEAD];              // [p][h]
__device__ float g_rpb[NHEAD * NTOK * NTOK];       // [h][n][m]

// ---------------- pos-bias MLP ----------------
__device__ __forceinline__ void ln16(float* x, const float* g, const float* b) {
    float m = 0.f;
#pragma unroll
    for (int i = 0; i < PD; i++) m += x[i];
    m *= (1.0f / PD);
    float v = 0.f;
#pragma unroll
    for (int i = 0; i < PD; i++) { float d = x[i] - m; v += d * d; }
    v *= (1.0f / PD);
    float inv = rsqrtf(v + 1e-5f);
#pragma unroll
    for (int i = 0; i < PD; i++) x[i] = (x[i] - m) * inv * g[i] + b[i];
}

__global__ void pos_mlp_kernel(const float* __restrict__ pp_w, const float* __restrict__ pp_b,
                               const float* __restrict__ ln1_g, const float* __restrict__ ln1_b,
                               const float* __restrict__ l1_w,  const float* __restrict__ l1_b,
                               const float* __restrict__ ln2_g, const float* __restrict__ ln2_b,
                               const float* __restrict__ l2_w,  const float* __restrict__ l2_b,
                               const float* __restrict__ ln3_g, const float* __restrict__ ln3_b,
                               const float* __restrict__ l3_w,  const float* __restrict__ l3_b) {
    int p = blockIdx.x * blockDim.x + threadIdx.x;
    if (p >= LREL) return;
    float b0 = (float)(p / 31 - 15);
    float b1 = (float)(p % 31 - 15);
    float x[PD], y[PD];
#pragma unroll
    for (int o = 0; o < PD; o++) x[o] = b0 * pp_w[o * 2 + 0] + b1 * pp_w[o * 2 + 1] + pp_b[o];
    ln16(x, ln1_g, ln1_b);
#pragma unroll
    for (int o = 0; o < PD; o++) {
        float s = l1_b[o];
#pragma unroll
        for (int i = 0; i < PD; i++) s += fmaxf(x[i], 0.f) * l1_w[o * PD + i];
        y[o] = s;
    }
#pragma unroll
    for (int o = 0; o < PD; o++) x[o] = y[o];
    ln16(x, ln2_g, ln2_b);
#pragma unroll
    for (int o = 0; o < PD; o++) {
        float s = l2_b[o];
#pragma unroll
        for (int i = 0; i < PD; i++) s += fmaxf(x[i], 0.f) * l2_w[o * PD + i];
        y[o] = s;
    }
#pragma unroll
    for (int o = 0; o < PD; o++) x[o] = y[o];
    ln16(x, ln3_g, ln3_b);
#pragma unroll
    for (int h = 0; h < NHEAD; h++) {
        float s = l3_b[h];
#pragma unroll
        for (int i = 0; i < PD; i++) s += fmaxf(x[i], 0.f) * l3_w[h * PD + i];
        g_pos[p * NHEAD + h] = s;
    }
}

__global__ void rpb_fill_kernel() {
    int i = blockIdx.x * 256 + threadIdx.x;     // up to 8*256*256 = 524288
    int h = i >> 16;
    int rem = i & 65535;
    int n = rem >> 8;
    int m = rem & 255;
    int di = (n >> 4) - (m >> 4) + 15;
    int dj = (n & 15) - (m & 15) + 15;
    g_rpb[i] = g_pos[(di * 31 + dj) * NHEAD + h];
}

// ---------------- fp32 SGEMM: C[M][Ncols] = A[M][K] @ W[Ncols][K]^T + bias ----------------
// BM=BN=128, BK=8, 256 threads, 8x8 per thread.
__global__ __launch_bounds__(256)
void gemm_nt(const float* __restrict__ A, const float* __restrict__ W,
             const float* __restrict__ bias, float* __restrict__ C,
             int M, int Ncols, int K) {
    __shared__ float As[8][128];
    __shared__ float Bs[8][128];
    int tid = threadIdx.x;
    int tx = tid & 15, ty = tid >> 4;
    int m0 = blockIdx.y * 128;
    int n0 = blockIdx.x * 128;
    float acc[8][8];
#pragma unroll
    for (int i = 0; i < 8; i++)
#pragma unroll
        for (int j = 0; j < 8; j++) acc[i][j] = 0.f;

    int lr = tid >> 1;            // 0..127
    int lk = (tid & 1) * 4;       // 0 or 4
    const float* Ap = A + (m0 + lr) * K + lk;
    const float* Wp = W + (n0 + lr) * K + lk;

    for (int k0 = 0; k0 < K; k0 += 8) {
        float4 a4 = *(const float4*)(Ap + k0);
        float4 b4 = *(const float4*)(Wp + k0);
        As[lk + 0][lr] = a4.x; As[lk + 1][lr] = a4.y; As[lk + 2][lr] = a4.z; As[lk + 3][lr] = a4.w;
        Bs[lk + 0][lr] = b4.x; Bs[lk + 1][lr] = b4.y; Bs[lk + 2][lr] = b4.z; Bs[lk + 3][lr] = b4.w;
        __syncthreads();
#pragma unroll
        for (int kk = 0; kk < 8; kk++) {
            float a[8], bb[8];
#pragma unroll
            for (int i = 0; i < 8; i++) a[i] = As[kk][ty * 8 + i];
#pragma unroll
            for (int j = 0; j < 8; j++) bb[j] = Bs[kk][tx * 8 + j];
#pragma unroll
            for (int i = 0; i < 8; i++)
#pragma unroll
                for (int j = 0; j < 8; j++) acc[i][j] += a[i] * bb[j];
        }
        __syncthreads();
    }
    float breg[8];
#pragma unroll
    for (int j = 0; j < 8; j++) breg[j] = bias[n0 + tx * 8 + j];
#pragma unroll
    for (int i = 0; i < 8; i++) {
        float* Cp = C + (m0 + ty * 8 + i) * Ncols + n0 + tx * 8;
#pragma unroll
        for (int j4 = 0; j4 < 2; j4++) {
            float4 o;
            o.x = acc[i][j4 * 4 + 0] + breg[j4 * 4 + 0];
            o.y = acc[i][j4 * 4 + 1] + breg[j4 * 4 + 1];
            o.z = acc[i][j4 * 4 + 2] + breg[j4 * 4 + 2];
            o.w = acc[i][j4 * 4 + 3] + breg[j4 * 4 + 3];
            *(float4*)(Cp + j4 * 4) = o;
        }
    }
}

// ---------------- fused attention ----------------
// grid (4 row-blocks, 8 heads, 256 batch), 256 threads.
// Thread t: row r = t/4, quad qd = t%4; owns columns c = j*16 + qd*4 + e (j<16, e<4).
#define KV_STRIDE 36
__global__ __launch_bounds__(256, 1)
void attn_kernel(const float* __restrict__ mask) {
    extern __shared__ float sm[];
    float* Ks = sm;                         // 256 * 36
    float* Vs = sm + NTOK * KV_STRIDE;      // 256 * 36
    int tid = threadIdx.x;
    int r0 = blockIdx.x * 64;
    int h = blockIdx.y;
    int b = blockIdx.z;

    // cooperative K/V load (coalesced 128B rows)
#pragma unroll
    for (int it = 0; it < 8; it++) {
        int u = tid + it * 256;             // 0..2047
        int n = u >> 3;
        int d4 = (u & 7) * 4;
        const float* src = g_kv + (b * NTOK + n) * (2 * DIMC) + h * HD + d4;
        *(float4*)(Ks + n * KV_STRIDE + d4) = *(const float4*)(src);
        *(float4*)(Vs + n * KV_STRIDE + d4) = *(const float4*)(src + DIMC);
    }

    int r = tid >> 2, qd = tid & 3;
    int rg = r0 + r;
    const float scale = 0.17677669529663687f;   // 32^-0.5
    float qreg[HD];
    {
        const float* qsrc = g_qh + (b * NTOK + rg) * DIMC + h * HD;
#pragma unroll
        for (int d4 = 0; d4 < 8; d4++) {
            float4 qq = *(const float4*)(qsrc + d4 * 4);
            qreg[d4 * 4 + 0] = qq.x * scale;
            qreg[d4 * 4 + 1] = qq.y * scale;
            qreg[d4 * 4 + 2] = qq.z * scale;
            qreg[d4 * 4 + 3] = qq.w * scale;
        }
    }
    __syncthreads();

    // scores
    float s[64];
#pragma unroll
    for (int j = 0; j < 16; j++) {
#pragma unroll
        for (int e = 0; e < 4; e++) {
            int c = j * 16 + qd * 4 + e;
            const float* kr = Ks + c * KV_STRIDE;
            float acc = 0.f;
#pragma unroll
            for (int d4 = 0; d4 < 8; d4++) {
                float4 k4 = *(const float4*)(kr + d4 * 4);
                acc += qreg[d4 * 4 + 0] * k4.x + qreg[d4 * 4 + 1] * k4.y
                     + qreg[d4 * 4 + 2] * k4.z + qreg[d4 * 4 + 3] * k4.w;
            }
            s[j * 4 + e] = acc;
        }
    }

    // + rpb + mask (coalesced float4 loads)
    const float* rpbRow  = g_rpb + (h * NTOK + rg) * NTOK;
    const float* maskRow = mask  + ((b & (NGROUP - 1)) * NTOK + rg) * NTOK;
#pragma unroll
    for (int j = 0; j < 16; j++) {
        int c0 = j * 16 + qd * 4;
        float4 rb = *(const float4*)(rpbRow + c0);
        float4 mk = *(const float4*)(maskRow + c0);
        s[j * 4 + 0] += rb.x + mk.x;
        s[j * 4 + 1] += rb.y + mk.y;
        s[j * 4 + 2] += rb.z + mk.z;
        s[j * 4 + 3] += rb.w + mk.w;
    }

    // softmax (row split across quad of 4 lanes)
    float mx = -1e30f;
#pragma unroll
    for (int i = 0; i < 64; i++) mx = fmaxf(mx, s[i]);
    mx = fmaxf(mx, __shfl_xor_sync(0xffffffffu, mx, 1));
    mx = fmaxf(mx, __shfl_xor_sync(0xffffffffu, mx, 2));
    float sum = 0.f;
#pragma unroll
    for (int i = 0; i < 64; i++) { s[i] = __expf(s[i] - mx); sum += s[i]; }
    sum += __shfl_xor_sync(0xffffffffu, sum, 1);
    sum += __shfl_xor_sync(0xffffffffu, sum, 2);
    float inv = 1.0f / sum;

    // O = P @ V
    float o[HD];
#pragma unroll
    for (int d = 0; d < HD; d++) o[d] = 0.f;
#pragma unroll
    for (int j = 0; j < 16; j++) {
#pragma unroll
        for (int e = 0; e < 4; e++) {
            int c = j * 16 + qd * 4 + e;
            float p = s[j * 4 + e];
            const float* vr = Vs + c * KV_STRIDE;
#pragma unroll
            for (int d4 = 0; d4 < 8; d4++) {
                float4 v4 = *(const float4*)(vr + d4 * 4);
                o[d4 * 4 + 0] += p * v4.x;
                o[d4 * 4 + 1] += p * v4.y;
                o[d4 * 4 + 2] += p * v4.z;
                o[d4 * 4 + 3] += p * v4.w;
            }
        }
    }
#pragma unroll
    for (int d = 0; d < HD; d++) {
        o[d] += __shfl_xor_sync(0xffffffffu, o[d], 1);
        o[d] += __shfl_xor_sync(0xffffffffu, o[d], 2);
        o[d] *= inv;
    }
    // each quad lane writes its 8 contiguous d's
    float* xo = g_x + (b * NTOK + rg) * DIMC + h * HD + qd * 8;
    float4 w0, w1;
    w0.x = o[qd * 8 + 0]; w0.y = o[qd * 8 + 1]; w0.z = o[qd * 8 + 2]; w0.w = o[qd * 8 + 3];
    w1.x = o[qd * 8 + 4]; w1.y = o[qd * 8 + 5]; w1.z = o[qd * 8 + 6]; w1.w = o[qd * 8 + 7];
    *(float4*)(xo) = w0;
    *(float4*)(xo + 4) = w1;
}

// ---------------- launch ----------------
extern "C" void kernel_launch(void* const* d_in, const int* in_sizes, int n_in,
                              void* d_out, int out_size) {
    const float* q      = (const float*)d_in[0];
    const float* k      = (const float*)d_in[1];
    const float* mask   = (const float*)d_in[2];
    const float* q_w    = (const float*)d_in[3];
    const float* q_b    = (const float*)d_in[4];
    const float* kv_w   = (const float*)d_in[5];
    const float* kv_b   = (const float*)d_in[6];
    const float* proj_w = (const float*)d_in[7];
    const float* proj_b = (const float*)d_in[8];
    const float* pp_w   = (const float*)d_in[9];
    const float* pp_b   = (const float*)d_in[10];
    const float* ln1_g  = (const float*)d_in[11];
    const float* ln1_b  = (const float*)d_in[12];
    const float* l1_w   = (const float*)d_in[13];
    const float* l1_b   = (const float*)d_in[14];
    const float* ln2_g  = (const float*)d_in[15];
    const float* ln2_b  = (const float*)d_in[16];
    const float* l2_w   = (const float*)d_in[17];
    const float* l2_b   = (const float*)d_in[18];
    const float* ln3_g  = (const float*)d_in[19];
    const float* ln3_b  = (const float*)d_in[20];
    const float* l3_w   = (const float*)d_in[21];
    const float* l3_b   = (const float*)d_in[22];
    (void)in_sizes; (void)n_in; (void)out_size;

    float *qh, *kv, *x;
    cudaGetSymbolAddress((void**)&qh, g_qh);
    cudaGetSymbolAddress((void**)&kv, g_kv);
    cudaGetSymbolAddress((void**)&x,  g_x);

    // position bias table
    pos_mlp_kernel<<<4, 256>>>(pp_w, pp_b, ln1_g, ln1_b, l1_w, l1_b,
                               ln2_g, ln2_b, l2_w, l2_b, ln3_g, ln3_b, l3_w, l3_b);
    rpb_fill_kernel<<<NHEAD * NTOK * NTOK / 256, 256>>>();

    const int M = BATCH * NTOK;   // 65536
    gemm_nt<<<dim3(DIMC / 128, M / 128), 256>>>(q, q_w, q_b, qh, M, DIMC, DIMC);
    gemm_nt<<<dim3(2 * DIMC / 128, M / 128), 256>>>(k, kv_w, kv_b, kv, M, 2 * DIMC, DIMC);

    int smem = 2 * NTOK * KV_STRIDE * (int)sizeof(float);   // 73728
    cudaFuncSetAttribute(attn_kernel, cudaFuncAttributeMaxDynamicSharedMemorySize, smem);
    attn_kernel<<<dim3(4, NHEAD, BATCH), 256, smem>>>(mask);

    gemm_nt<<<dim3(DIMC / 128, M / 128), 256>>>(x, proj_w, proj_b, (float*)d_out, M, DIMC, DIMC);
}

// round 3
// speedup vs baseline: 1.9944x; 1.9944x over previous
#include <cuda_runtime.h>
#include <cstdint>
#include <cstddef>

// ---------------- problem constants ----------------
#define NHEAD 8
#define HD 32
#define NTOK 256
#define BATCH 256
#define DIMC 256
#define NGROUP 64
#define PD 16
#define LREL 961   // (2*16-1)^2

// ---------------- device scratch ----------------
__device__ float g_qh[BATCH * NTOK * DIMC];
__device__ float g_kv[BATCH * NTOK * 2 * DIMC];
__device__ float g_x [BATCH * NTOK * DIMC];
__device__ float g_pos[LREL * NHEAD];
__device__ float g_rpb[NHEAD * NTOK * NTOK];

// ---------------- mma.sync tf32 helpers ----------------
__device__ __forceinline__ void split_tf32(float x, uint32_t& hi, uint32_t& lo) {
    asm("cvt.rna.tf32.f32 %0, %1;" : "=r"(hi) : "f"(x));
    float r = x - __uint_as_float(hi);
    asm("cvt.rna.tf32.f32 %0, %1;" : "=r"(lo) : "f"(r));
}
__device__ __forceinline__ void mma_tf32(float* d, const uint32_t* a, const uint32_t* b) {
    asm volatile("mma.sync.aligned.m16n8k8.row.col.f32.tf32.tf32.f32 "
        "{%0,%1,%2,%3}, {%4,%5,%6,%7}, {%8,%9}, {%0,%1,%2,%3};"
        : "+f"(d[0]), "+f"(d[1]), "+f"(d[2]), "+f"(d[3])
        : "r"(a[0]), "r"(a[1]), "r"(a[2]), "r"(a[3]), "r"(b[0]), "r"(b[1]));
}

// ---------------- pos-bias MLP ----------------
__device__ __forceinline__ void ln16(float* x, const float* g, const float* b) {
    float m = 0.f;
#pragma unroll
    for (int i = 0; i < PD; i++) m += x[i];
    m *= (1.0f / PD);
    float v = 0.f;
#pragma unroll
    for (int i = 0; i < PD; i++) { float d = x[i] - m; v += d * d; }
    v *= (1.0f / PD);
    float inv = rsqrtf(v + 1e-5f);
#pragma unroll
    for (int i = 0; i < PD; i++) x[i] = (x[i] - m) * inv * g[i] + b[i];
}

__global__ void pos_mlp_kernel(const float* __restrict__ pp_w, const float* __restrict__ pp_b,
                               const float* __restrict__ ln1_g, const float* __restrict__ ln1_b,
                               const float* __restrict__ l1_w,  const float* __restrict__ l1_b,
                               const float* __restrict__ ln2_g, const float* __restrict__ ln2_b,
                               const float* __restrict__ l2_w,  const float* __restrict__ l2_b,
                               const float* __restrict__ ln3_g, const float* __restrict__ ln3_b,
                               const float* __restrict__ l3_w,  const float* __restrict__ l3_b) {
    int p = blockIdx.x * blockDim.x + threadIdx.x;
    if (p >= LREL) return;
    float b0 = (float)(p / 31 - 15);
    float b1 = (float)(p % 31 - 15);
    float x[PD], y[PD];
#pragma unroll
    for (int o = 0; o < PD; o++) x[o] = b0 * pp_w[o * 2 + 0] + b1 * pp_w[o * 2 + 1] + pp_b[o];
    ln16(x, ln1_g, ln1_b);
#pragma unroll
    for (int o = 0; o < PD; o++) {
        float s = l1_b[o];
#pragma unroll
        for (int i = 0; i < PD; i++) s += fmaxf(x[i], 0.f) * l1_w[o * PD + i];
        y[o] = s;
    }
#pragma unroll
    for (int o = 0; o < PD; o++) x[o] = y[o];
    ln16(x, ln2_g, ln2_b);
#pragma unroll
    for (int o = 0; o < PD; o++) {
        float s = l2_b[o];
#pragma unroll
        for (int i = 0; i < PD; i++) s += fmaxf(x[i], 0.f) * l2_w[o * PD + i];
        y[o] = s;
    }
#pragma unroll
    for (int o = 0; o < PD; o++) x[o] = y[o];
    ln16(x, ln3_g, ln3_b);
#pragma unroll
    for (int h = 0; h < NHEAD; h++) {
        float s = l3_b[h];
#pragma unroll
        for (int i = 0; i < PD; i++) s += fmaxf(x[i], 0.f) * l3_w[h * PD + i];
        g_pos[p * NHEAD + h] = s;
    }
}

__global__ void rpb_fill_kernel() {
    int i = blockIdx.x * 256 + threadIdx.x;
    int h = i >> 16;
    int rem = i & 65535;
    int n = rem >> 8;
    int m = rem & 255;
    int di = (n >> 4) - (m >> 4) + 15;
    int dj = (n & 15) - (m & 15) + 15;
    g_rpb[i] = g_pos[(di * 31 + dj) * NHEAD + h];
}

// ---------------- tf32 mma.sync GEMM (3xTF32 precision) ----------------
// C[M][Ncols] = A[M][K] @ W[Ncols][K]^T + bias. CTA tile 128x128, K chunk 32.
// 8 warps in 2(m) x 4(n); warp tile 64x32 = 4 m-atoms x 4 n-atoms of m16n8k8.
#define GST 36
__global__ __launch_bounds__(256)
void gemm_mma(const float* __restrict__ A, const float* __restrict__ W,
              const float* __restrict__ bias, float* __restrict__ C,
              int M, int Ncols, int K) {
    extern __shared__ float gs[];
    const int STAGE = 2 * 128 * GST;
    int tid = threadIdx.x, lane = tid & 31, wid = tid >> 5;
    int m0 = blockIdx.y * 128, n0 = blockIdx.x * 128;
    int wm = (wid >> 2) * 64, wn = (wid & 3) * 32;
    int g = lane >> 2, tg = lane & 3;

    float acc[4][4][4];
#pragma unroll
    for (int a = 0; a < 4; a++)
#pragma unroll
        for (int bq = 0; bq < 4; bq++)
#pragma unroll
            for (int c = 0; c < 4; c++) acc[a][bq][c] = 0.f;

    int lrow = tid >> 3;
    int lc4 = (tid & 7) * 4;

    {   // preload chunk 0 into stage 0
        float* sA = gs; float* sB = gs + 128 * GST;
#pragma unroll
        for (int it = 0; it < 4; it++) {
            int row = it * 32 + lrow;
            *(float4*)(sA + row * GST + lc4) = *(const float4*)(A + (size_t)(m0 + row) * K + lc4);
            *(float4*)(sB + row * GST + lc4) = *(const float4*)(W + (size_t)(n0 + row) * K + lc4);
        }
    }
    __syncthreads();

    int nch = K >> 5;
    for (int kc = 0; kc < nch; kc++) {
        int s = kc & 1;
        if (kc + 1 < nch) {
            float* sA = gs + (s ^ 1) * STAGE; float* sB = sA + 128 * GST;
            const float* Ap = A + (kc + 1) * 32;
            const float* Wp = W + (kc + 1) * 32;
#pragma unroll
            for (int it = 0; it < 4; it++) {
                int row = it * 32 + lrow;
                *(float4*)(sA + row * GST + lc4) = *(const float4*)(Ap + (size_t)(m0 + row) * K + lc4);
                *(float4*)(sB + row * GST + lc4) = *(const float4*)(Wp + (size_t)(n0 + row) * K + lc4);
            }
        }
        float* sA = gs + s * STAGE; float* sB = sA + 128 * GST;
#pragma unroll
        for (int ks = 0; ks < 4; ks++) {
            uint32_t ah[4][4], al[4][4], bh[4][2], bl[4][2];
#pragma unroll
            for (int mt = 0; mt < 4; mt++) {
                const float* p = sA + (wm + mt * 16 + g) * GST + ks * 8 + tg;
                split_tf32(p[0],           ah[mt][0], al[mt][0]);
                split_tf32(p[8 * GST],     ah[mt][1], al[mt][1]);
                split_tf32(p[4],           ah[mt][2], al[mt][2]);
                split_tf32(p[8 * GST + 4], ah[mt][3], al[mt][3]);
            }
#pragma unroll
            for (int nt = 0; nt < 4; nt++) {
                const float* p = sB + (wn + nt * 8 + g) * GST + ks * 8 + tg;
                split_tf32(p[0], bh[nt][0], bl[nt][0]);
                split_tf32(p[4], bh[nt][1], bl[nt][1]);
            }
#pragma unroll
            for (int mt = 0; mt < 4; mt++)
#pragma unroll
                for (int nt = 0; nt < 4; nt++) {
                    mma_tf32(acc[mt][nt], ah[mt], bh[nt]);
                    mma_tf32(acc[mt][nt], ah[mt], bl[nt]);
                    mma_tf32(acc[mt][nt], al[mt], bh[nt]);
                }
        }
        __syncthreads();
    }

    // epilogue: C layout — thread holds rows g, g+8; cols 2*tg, 2*tg+1 per atom
#pragma unroll
    for (int mt = 0; mt < 4; mt++) {
        int r0 = m0 + wm + mt * 16 + g;
#pragma unroll
        for (int nt = 0; nt < 4; nt++) {
            int col = n0 + wn + nt * 8 + 2 * tg;
            float bb0 = bias[col], bb1 = bias[col + 1];
            float2 v0, v1;
            v0.x = acc[mt][nt][0] + bb0; v0.y = acc[mt][nt][1] + bb1;
            v1.x = acc[mt][nt][2] + bb0; v1.y = acc[mt][nt][3] + bb1;
            *(float2*)(C + (size_t)r0 * Ncols + col) = v0;
            *(float2*)(C + (size_t)(r0 + 8) * Ncols + col) = v1;
        }
    }
}

// ---------------- fused attention (register-blocked, 2 rows/thread) ----------------
// grid (4, 8, 256), 256 threads. rt = tid>>3 owns rows r0+2*rt, +1; ct = tid&7
// owns cols c = j*8 + ct (j<32). Stride-36 smem: conflict-free broadcast LDS.
#define AST 36
__global__ __launch_bounds__(256, 1)
void attn_kernel(const float* __restrict__ mask) {
    extern __shared__ float sm[];
    float* Qs = sm;                    // 64 * 36
    float* Ks = sm + 64 * AST;         // 256 * 36
    float* Vs = Ks + 256 * AST;        // 256 * 36
    int tid = threadIdx.x;
    int r0 = blockIdx.x * 64, h = blockIdx.y, b = blockIdx.z;
    int rt = tid >> 3, ct = tid & 7;

    {
        int dd4 = (tid & 7) * 4;
        const float scale = 0.17677669529663687f;   // 32^-0.5
#pragma unroll
        for (int it = 0; it < 8; it++) {
            int nn = it * 32 + (tid >> 3);
            const float* src = g_kv + (size_t)(b * NTOK + nn) * (2 * DIMC) + h * HD + dd4;
            *(float4*)(Ks + nn * AST + dd4) = *(const float4*)src;
            *(float4*)(Vs + nn * AST + dd4) = *(const float4*)(src + DIMC);
        }
#pragma unroll
        for (int it = 0; it < 2; it++) {
            int rr = it * 32 + (tid >> 3);
            float4 qv = *(const float4*)(g_qh + (size_t)(b * NTOK + r0 + rr) * DIMC + h * HD + dd4);
            qv.x *= scale; qv.y *= scale; qv.z *= scale; qv.w *= scale;
            *(float4*)(Qs + rr * AST + dd4) = qv;
        }
    }
    __syncthreads();

    int ra = rt * 2, rb = ra + 1;
    float s0[32], s1[32];
#pragma unroll
    for (int j = 0; j < 32; j++) { s0[j] = 0.f; s1[j] = 0.f; }

    for (int dd = 0; dd < 8; dd++) {              // dynamic: keeps code small
        float4 qa = *(const float4*)(Qs + ra * AST + dd * 4);
        float4 qb = *(const float4*)(Qs + rb * AST + dd * 4);
#pragma unroll
        for (int j = 0; j < 32; j++) {
            float4 k4 = *(const float4*)(Ks + (j * 8 + ct) * AST + dd * 4);
            s0[j] += qa.x * k4.x + qa.y * k4.y + qa.z * k4.z + qa.w * k4.w;
            s1[j] += qb.x * k4.x + qb.y * k4.y + qb.z * k4.z + qb.w * k4.w;
        }
    }

    // + rpb + mask
    const float* rpb0 = g_rpb + ((size_t)h * NTOK + (r0 + ra)) * NTOK;
    const float* rpb1 = rpb0 + NTOK;
    const float* mk0  = mask + ((size_t)(b & (NGROUP - 1)) * NTOK + (r0 + ra)) * NTOK;
    const float* mk1  = mk0 + NTOK;
#pragma unroll
    for (int j = 0; j < 32; j++) {
        int c = j * 8 + ct;
        s0[j] += rpb0[c] + mk0[c];
        s1[j] += rpb1[c] + mk1[c];
    }

    // softmax across the 8-lane (ct) group
    float mx0 = -1e30f, mx1 = -1e30f;
#pragma unroll
    for (int j = 0; j < 32; j++) { mx0 = fmaxf(mx0, s0[j]); mx1 = fmaxf(mx1, s1[j]); }
#pragma unroll
    for (int w = 1; w <= 4; w <<= 1) {
        mx0 = fmaxf(mx0, __shfl_xor_sync(0xffffffffu, mx0, w));
        mx1 = fmaxf(mx1, __shfl_xor_sync(0xffffffffu, mx1, w));
    }
    float sum0 = 0.f, sum1 = 0.f;
#pragma unroll
    for (int j = 0; j < 32; j++) {
        s0[j] = __expf(s0[j] - mx0); sum0 += s0[j];
        s1[j] = __expf(s1[j] - mx1); sum1 += s1[j];
    }
#pragma unroll
    for (int w = 1; w <= 4; w <<= 1) {
        sum0 += __shfl_xor_sync(0xffffffffu, sum0, w);
        sum1 += __shfl_xor_sync(0xffffffffu, sum1, w);
    }
    float inv0 = 1.0f / sum0, inv1 = 1.0f / sum1;

    // O = P @ V (partial over owned cols)
    float o0[32], o1[32];
#pragma unroll
    for (int d = 0; d < 32; d++) { o0[d] = 0.f; o1[d] = 0.f; }
#pragma unroll
    for (int j = 0; j < 32; j++) {
        int c = j * 8 + ct;
        float p0 = s0[j], p1 = s1[j];
#pragma unroll
        for (int dd = 0; dd < 8; dd++) {
            float4 v4 = *(const float4*)(Vs + c * AST + dd * 4);
            o0[dd * 4 + 0] += p0 * v4.x; o0[dd * 4 + 1] += p0 * v4.y;
            o0[dd * 4 + 2] += p0 * v4.z; o0[dd * 4 + 3] += p0 * v4.w;
            o1[dd * 4 + 0] += p1 * v4.x; o1[dd * 4 + 1] += p1 * v4.y;
            o1[dd * 4 + 2] += p1 * v4.z; o1[dd * 4 + 3] += p1 * v4.w;
        }
    }

    // reduce-scatter across the 8 ct lanes: lane ct ends with d = ct*4..ct*4+3
    float a0[16], a1[16];
#pragma unroll
    for (int i = 0; i < 16; i++) {
        float keep0 = (ct & 4) ? o0[16 + i] : o0[i];
        float give0 = (ct & 4) ? o0[i] : o0[16 + i];
        a0[i] = keep0 + __shfl_xor_sync(0xffffffffu, give0, 4);
        float keep1 = (ct & 4) ? o1[16 + i] : o1[i];
        float give1 = (ct & 4) ? o1[i] : o1[16 + i];
        a1[i] = keep1 + __shfl_xor_sync(0xffffffffu, give1, 4);
    }
    float c0[8], c1[8];
#pragma unroll
    for (int i = 0; i < 8; i++) {
        float keep0 = (ct & 2) ? a0[8 + i] : a0[i];
        float give0 = (ct & 2) ? a0[i] : a0[8 + i];
        c0[i] = keep0 + __shfl_xor_sync(0xffffffffu, give0, 2);
        float keep1 = (ct & 2) ? a1[8 + i] : a1[i];
        float give1 = (ct & 2) ? a1[i] : a1[8 + i];
        c1[i] = keep1 + __shfl_xor_sync(0xffffffffu, give1, 2);
    }
    float f0[4], f1[4];
#pragma unroll
    for (int i = 0; i < 4; i++) {
        float keep0 = (ct & 1) ? c0[4 + i] : c0[i];
        float give0 = (ct & 1) ? c0[i] : c0[4 + i];
        f0[i] = keep0 + __shfl_xor_sync(0xffffffffu, give0, 1);
        float keep1 = (ct & 1) ? c1[4 + i] : c1[i];
        float give1 = (ct & 1) ? c1[i] : c1[4 + i];
        f1[i] = keep1 + __shfl_xor_sync(0xffffffffu, give1, 1);
    }
    float4 w0, w1;
    w0.x = f0[0] * inv0; w0.y = f0[1] * inv0; w0.z = f0[2] * inv0; w0.w = f0[3] * inv0;
    w1.x = f1[0] * inv1; w1.y = f1[1] * inv1; w1.z = f1[2] * inv1; w1.w = f1[3] * inv1;
    *(float4*)(g_x + (size_t)(b * NTOK + r0 + ra) * DIMC + h * HD + ct * 4) = w0;
    *(float4*)(g_x + (size_t)(b * NTOK + r0 + rb) * DIMC + h * HD + ct * 4) = w1;
}

// ---------------- launch ----------------
extern "C" void kernel_launch(void* const* d_in, const int* in_sizes, int n_in,
                              void* d_out, int out_size) {
    const float* q      = (const float*)d_in[0];
    const float* k      = (const float*)d_in[1];
    const float* mask   = (const float*)d_in[2];
    const float* q_w    = (const float*)d_in[3];
    const float* q_b    = (const float*)d_in[4];
    const float* kv_w   = (const float*)d_in[5];
    const float* kv_b   = (const float*)d_in[6];
    const float* proj_w = (const float*)d_in[7];
    const float* proj_b = (const float*)d_in[8];
    const float* pp_w   = (const float*)d_in[9];
    const float* pp_b   = (const float*)d_in[10];
    const float* ln1_g  = (const float*)d_in[11];
    const float* ln1_b  = (const float*)d_in[12];
    const float* l1_w   = (const float*)d_in[13];
    const float* l1_b   = (const float*)d_in[14];
    const float* ln2_g  = (const float*)d_in[15];
    const float* ln2_b  = (const float*)d_in[16];
    const float* l2_w   = (const float*)d_in[17];
    const float* l2_b   = (const float*)d_in[18];
    const float* ln3_g  = (const float*)d_in[19];
    const float* ln3_b  = (const float*)d_in[20];
    const float* l3_w   = (const float*)d_in[21];
    const float* l3_b   = (const float*)d_in[22];
    (void)in_sizes; (void)n_in; (void)out_size;

    float *qh, *kv, *x;
    cudaGetSymbolAddress((void**)&qh, g_qh);
    cudaGetSymbolAddress((void**)&kv, g_kv);
    cudaGetSymbolAddress((void**)&x,  g_x);

    int gsmem = 2 * 2 * 128 * GST * (int)sizeof(float);        // 73728
    int asmem = (64 + 2 * NTOK) * AST * (int)sizeof(float);    // 82944
    static int attr_done = 0;
    if (!attr_done) {
        cudaFuncSetAttribute(gemm_mma, cudaFuncAttributeMaxDynamicSharedMemorySize, gsmem);
        cudaFuncSetAttribute(attn_kernel, cudaFuncAttributeMaxDynamicSharedMemorySize, asmem);
        attr_done = 1;
    }

    pos_mlp_kernel<<<4, 256>>>(pp_w, pp_b, ln1_g, ln1_b, l1_w, l1_b,
                               ln2_g, ln2_b, l2_w, l2_b, ln3_g, ln3_b, l3_w, l3_b);
    rpb_fill_kernel<<<NHEAD * NTOK * NTOK / 256, 256>>>();

    const int M = BATCH * NTOK;   // 65536
    gemm_mma<<<dim3(DIMC / 128, M / 128), 256, gsmem>>>(q, q_w, q_b, qh, M, DIMC, DIMC);
    gemm_mma<<<dim3(2 * DIMC / 128, M / 128), 256, gsmem>>>(k, kv_w, kv_b, kv, M, 2 * DIMC, DIMC);

    attn_kernel<<<dim3(4, NHEAD, BATCH), 256, asmem>>>(mask);

    gemm_mma<<<dim3(DIMC / 128, M / 128), 256, gsmem>>>(x, proj_w, proj_b, (float*)d_out, M, DIMC, DIMC);
}

// round 4
// speedup vs baseline: 2.2541x; 1.1302x over previous
#include <cuda_runtime.h>
#include <cuda_bf16.h>
#include <cuda_fp16.h>
#include <cstdint>
#include <cstddef>

// ---------------- problem constants ----------------
#define NHEAD 8
#define HD 32
#define NTOK 256
#define BATCH 256
#define DIMC 256
#define NGROUP 64
#define PD 16
#define LREL 961   // (2*16-1)^2

// ---------------- device scratch ----------------
__device__ float g_qh[BATCH * NTOK * DIMC];
__device__ float g_kv[BATCH * NTOK * 2 * DIMC];
__device__ float g_x [BATCH * NTOK * DIMC];
__device__ float g_pos[LREL * NHEAD];
__device__ float g_rpb[NHEAD * NTOK * NTOK];

// ---------------- mma helpers ----------------
__device__ __forceinline__ void pack_bf16_pair(float x, float y, uint32_t& hi, uint32_t& lo) {
    __nv_bfloat16 hx = __float2bfloat16_rn(x);
    __nv_bfloat16 hy = __float2bfloat16_rn(y);
    float rx = x - __bfloat162float(hx);
    float ry = y - __bfloat162float(hy);
    __nv_bfloat16 lx = __float2bfloat16_rn(rx);
    __nv_bfloat16 ly = __float2bfloat16_rn(ry);
    hi = ((uint32_t)__bfloat16_as_ushort(hy) << 16) | (uint32_t)__bfloat16_as_ushort(hx);
    lo = ((uint32_t)__bfloat16_as_ushort(ly) << 16) | (uint32_t)__bfloat16_as_ushort(lx);
}
__device__ __forceinline__ void mma_bf16(float* d, const uint32_t* a, const uint32_t* b) {
    asm volatile("mma.sync.aligned.m16n8k16.row.col.f32.bf16.bf16.f32 "
        "{%0,%1,%2,%3}, {%4,%5,%6,%7}, {%8,%9}, {%0,%1,%2,%3};"
        : "+f"(d[0]), "+f"(d[1]), "+f"(d[2]), "+f"(d[3])
        : "r"(a[0]), "r"(a[1]), "r"(a[2]), "r"(a[3]), "r"(b[0]), "r"(b[1]));
}

// ---------------- pos-bias MLP ----------------
__device__ __forceinline__ void ln16(float* x, const float* g, const float* b) {
    float m = 0.f;
#pragma unroll
    for (int i = 0; i < PD; i++) m += x[i];
    m *= (1.0f / PD);
    float v = 0.f;
#pragma unroll
    for (int i = 0; i < PD; i++) { float d = x[i] - m; v += d * d; }
    v *= (1.0f / PD);
    float inv = rsqrtf(v + 1e-5f);
#pragma unroll
    for (int i = 0; i < PD; i++) x[i] = (x[i] - m) * inv * g[i] + b[i];
}

__global__ void pos_mlp_kernel(const float* __restrict__ pp_w, const float* __restrict__ pp_b,
                               const float* __restrict__ ln1_g, const float* __restrict__ ln1_b,
                               const float* __restrict__ l1_w,  const float* __restrict__ l1_b,
                               const float* __restrict__ ln2_g, const float* __restrict__ ln2_b,
                               const float* __restrict__ l2_w,  const float* __restrict__ l2_b,
                               const float* __restrict__ ln3_g, const float* __restrict__ ln3_b,
                               const float* __restrict__ l3_w,  const float* __restrict__ l3_b) {
    int p = blockIdx.x * blockDim.x + threadIdx.x;
    if (p >= LREL) return;
    float b0 = (float)(p / 31 - 15);
    float b1 = (float)(p % 31 - 15);
    float x[PD], y[PD];
#pragma unroll
    for (int o = 0; o < PD; o++) x[o] = b0 * pp_w[o * 2 + 0] + b1 * pp_w[o * 2 + 1] + pp_b[o];
    ln16(x, ln1_g, ln1_b);
#pragma unroll
    for (int o = 0; o < PD; o++) {
        float s = l1_b[o];
#pragma unroll
        for (int i = 0; i < PD; i++) s += fmaxf(x[i], 0.f) * l1_w[o * PD + i];
        y[o] = s;
    }
#pragma unroll
    for (int o = 0; o < PD; o++) x[o] = y[o];
    ln16(x, ln2_g, ln2_b);
#pragma unroll
    for (int o = 0; o < PD; o++) {
        float s = l2_b[o];
#pragma unroll
        for (int i = 0; i < PD; i++) s += fmaxf(x[i], 0.f) * l2_w[o * PD + i];
        y[o] = s;
    }
#pragma unroll
    for (int o = 0; o < PD; o++) x[o] = y[o];
    ln16(x, ln3_g, ln3_b);
#pragma unroll
    for (int h = 0; h < NHEAD; h++) {
        float s = l3_b[h];
#pragma unroll
        for (int i = 0; i < PD; i++) s += fmaxf(x[i], 0.f) * l3_w[h * PD + i];
        g_pos[p * NHEAD + h] = s;
    }
}

__global__ void rpb_fill_kernel() {
    int i = blockIdx.x * 256 + threadIdx.x;
    int h = i >> 16;
    int rem = i & 65535;
    int n = rem >> 8;
    int m = rem & 255;
    int di = (n >> 4) - (m >> 4) + 15;
    int dj = (n & 15) - (m & 15) + 15;
    g_rpb[i] = g_pos[(di * 31 + dj) * NHEAD + h];
}

// ---------------- bf16-split mma.sync GEMM ----------------
// C[M][Ncols] = A[M][K] @ W[Ncols][K]^T + bias. CTA tile 128x128, K chunk 32.
// SMEM: per stage 4 sub-tiles (Ahi, Alo, Bhi, Blo), each 128 rows x 16 packed
// u32 k-pairs, stride GPAD=20 (conflict-free fragment loads).
#define GPAD 20
#define GTILE (128 * GPAD)            // u32 per sub-tile
#define GSTAGE (4 * GTILE)            // u32 per stage
__global__ __launch_bounds__(256)
void gemm_bf16(const float* __restrict__ A, const float* __restrict__ W,
               const float* __restrict__ bias, float* __restrict__ C,
               int M, int Ncols, int K) {
    extern __shared__ uint32_t gsm[];
    int tid = threadIdx.x, lane = tid & 31, wid = tid >> 5;
    int m0 = blockIdx.y * 128, n0 = blockIdx.x * 128;
    int wm = (wid >> 2) * 64, wn = (wid & 3) * 32;
    int g = lane >> 2, tg = lane & 3;

    float acc[4][4][4];
#pragma unroll
    for (int a = 0; a < 4; a++)
#pragma unroll
        for (int bq = 0; bq < 4; bq++)
#pragma unroll
            for (int c = 0; c < 4; c++) acc[a][bq][c] = 0.f;

    int lrow = tid >> 3;          // 0..31
    int lc4 = (tid & 7) * 4;      // float col 0..28 step 4
    int lp = lc4 >> 1;            // pair col 0..14 step 2

    // chunk loader: reads 32 fp32 per thread, splits to bf16 hi/lo pairs
    {
        uint32_t* sAhi = gsm;             uint32_t* sAlo = gsm + GTILE;
        uint32_t* sBhi = gsm + 2 * GTILE; uint32_t* sBlo = gsm + 3 * GTILE;
#pragma unroll
        for (int it = 0; it < 4; it++) {
            int row = it * 32 + lrow;
            float4 a4 = *(const float4*)(A + (size_t)(m0 + row) * K + lc4);
            float4 b4 = *(const float4*)(W + (size_t)(n0 + row) * K + lc4);
            uint32_t h0, l0, h1, l1;
            pack_bf16_pair(a4.x, a4.y, h0, l0); pack_bf16_pair(a4.z, a4.w, h1, l1);
            sAhi[row * GPAD + lp] = h0; sAhi[row * GPAD + lp + 1] = h1;
            sAlo[row * GPAD + lp] = l0; sAlo[row * GPAD + lp + 1] = l1;
            pack_bf16_pair(b4.x, b4.y, h0, l0); pack_bf16_pair(b4.z, b4.w, h1, l1);
            sBhi[row * GPAD + lp] = h0; sBhi[row * GPAD + lp + 1] = h1;
            sBlo[row * GPAD + lp] = l0; sBlo[row * GPAD + lp + 1] = l1;
        }
    }
    __syncthreads();

    int nch = K >> 5;
    for (int kc = 0; kc < nch; kc++) {
        int s = kc & 1;
        if (kc + 1 < nch) {
            uint32_t* st = gsm + (s ^ 1) * GSTAGE;
            uint32_t* sAhi = st;             uint32_t* sAlo = st + GTILE;
            uint32_t* sBhi = st + 2 * GTILE; uint32_t* sBlo = st + 3 * GTILE;
            const float* Ap = A + (kc + 1) * 32;
            const float* Wp = W + (kc + 1) * 32;
#pragma unroll
            for (int it = 0; it < 4; it++) {
                int row = it * 32 + lrow;
                float4 a4 = *(const float4*)(Ap + (size_t)(m0 + row) * K + lc4);
                float4 b4 = *(const float4*)(Wp + (size_t)(n0 + row) * K + lc4);
                uint32_t h0, l0, h1, l1;
                pack_bf16_pair(a4.x, a4.y, h0, l0); pack_bf16_pair(a4.z, a4.w, h1, l1);
                sAhi[row * GPAD + lp] = h0; sAhi[row * GPAD + lp + 1] = h1;
                sAlo[row * GPAD + lp] = l0; sAlo[row * GPAD + lp + 1] = l1;
                pack_bf16_pair(b4.x, b4.y, h0, l0); pack_bf16_pair(b4.z, b4.w, h1, l1);
                sBhi[row * GPAD + lp] = h0; sBhi[row * GPAD + lp + 1] = h1;
                sBlo[row * GPAD + lp] = l0; sBlo[row * GPAD + lp + 1] = l1;
            }
        }
        uint32_t* st = gsm + s * GSTAGE;
        uint32_t* sAhi = st;             uint32_t* sAlo = st + GTILE;
        uint32_t* sBhi = st + 2 * GTILE; uint32_t* sBlo = st + 3 * GTILE;
#pragma unroll
        for (int ks = 0; ks < 2; ks++) {
            int pc = ks * 8 + tg;
            uint32_t ahi[4][4], alo[4][4], bhi[4][2], blo[4][2];
#pragma unroll
            for (int mt = 0; mt < 4; mt++) {
                int base = (wm + mt * 16 + g) * GPAD + pc;
                ahi[mt][0] = sAhi[base];              alo[mt][0] = sAlo[base];
                ahi[mt][1] = sAhi[base + 8 * GPAD];   alo[mt][1] = sAlo[base + 8 * GPAD];
                ahi[mt][2] = sAhi[base + 4];          alo[mt][2] = sAlo[base + 4];
                ahi[mt][3] = sAhi[base + 8 * GPAD + 4]; alo[mt][3] = sAlo[base + 8 * GPAD + 4];
            }
#pragma unroll
            for (int nt = 0; nt < 4; nt++) {
                int base = (wn + nt * 8 + g) * GPAD + pc;
                bhi[nt][0] = sBhi[base]; bhi[nt][1] = sBhi[base + 4];
                blo[nt][0] = sBlo[base]; blo[nt][1] = sBlo[base + 4];
            }
#pragma unroll
            for (int mt = 0; mt < 4; mt++)
#pragma unroll
                for (int nt = 0; nt < 4; nt++) {
                    mma_bf16(acc[mt][nt], ahi[mt], bhi[nt]);
                    mma_bf16(acc[mt][nt], ahi[mt], blo[nt]);
                    mma_bf16(acc[mt][nt], alo[mt], bhi[nt]);
                }
        }
        __syncthreads();
    }

    // epilogue: thread holds rows g, g+8; cols 2tg, 2tg+1 per atom
#pragma unroll
    for (int mt = 0; mt < 4; mt++) {
        int r0 = m0 + wm + mt * 16 + g;
#pragma unroll
        for (int nt = 0; nt < 4; nt++) {
            int col = n0 + wn + nt * 8 + 2 * tg;
            float bb0 = bias[col], bb1 = bias[col + 1];
            float2 v0, v1;
            v0.x = acc[mt][nt][0] + bb0; v0.y = acc[mt][nt][1] + bb1;
            v1.x = acc[mt][nt][2] + bb0; v1.y = acc[mt][nt][3] + bb1;
            *(float2*)(C + (size_t)r0 * Ncols + col) = v0;
            *(float2*)(C + (size_t)(r0 + 8) * Ncols + col) = v1;
        }
    }
}

// ---------------- fused attention (register-blocked, h2exp softmax) ----------------
#define AST 36
__global__ __launch_bounds__(256, 1)
void attn_kernel(const float* __restrict__ mask) {
    extern __shared__ float sm[];
    float* Qs = sm;                    // 64 * 36
    float* Ks = sm + 64 * AST;         // 256 * 36
    float* Vs = Ks + 256 * AST;        // 256 * 36
    int tid = threadIdx.x;
    int r0 = blockIdx.x * 64, h = blockIdx.y, b = blockIdx.z;
    int rt = tid >> 3, ct = tid & 7;

    {
        int dd4 = (tid & 7) * 4;
        const float scale = 0.17677669529663687f;   // 32^-0.5
#pragma unroll
        for (int it = 0; it < 8; it++) {
            int nn = it * 32 + (tid >> 3);
            const float* src = g_kv + (size_t)(b * NTOK + nn) * (2 * DIMC) + h * HD + dd4;
            *(float4*)(Ks + nn * AST + dd4) = *(const float4*)src;
            *(float4*)(Vs + nn * AST + dd4) = *(const float4*)(src + DIMC);
        }
#pragma unroll
        for (int it = 0; it < 2; it++) {
            int rr = it * 32 + (tid >> 3);
            float4 qv = *(const float4*)(g_qh + (size_t)(b * NTOK + r0 + rr) * DIMC + h * HD + dd4);
            qv.x *= scale; qv.y *= scale; qv.z *= scale; qv.w *= scale;
            *(float4*)(Qs + rr * AST + dd4) = qv;
        }
    }
    __syncthreads();

    int ra = rt * 2, rb = ra + 1;
    float s0[32], s1[32];
#pragma unroll
    for (int j = 0; j < 32; j++) { s0[j] = 0.f; s1[j] = 0.f; }

    for (int dd = 0; dd < 8; dd++) {
        float4 qa = *(const float4*)(Qs + ra * AST + dd * 4);
        float4 qb = *(const float4*)(Qs + rb * AST + dd * 4);
#pragma unroll
        for (int j = 0; j < 32; j++) {
            float4 k4 = *(const float4*)(Ks + (j * 8 + ct) * AST + dd * 4);
            s0[j] += qa.x * k4.x + qa.y * k4.y + qa.z * k4.z + qa.w * k4.w;
            s1[j] += qb.x * k4.x + qb.y * k4.y + qb.z * k4.z + qb.w * k4.w;
        }
    }

    const float* rpb0 = g_rpb + ((size_t)h * NTOK + (r0 + ra)) * NTOK;
    const float* rpb1 = rpb0 + NTOK;
    const float* mk0  = mask + ((size_t)(b & (NGROUP - 1)) * NTOK + (r0 + ra)) * NTOK;
    const float* mk1  = mk0 + NTOK;
#pragma unroll
    for (int j = 0; j < 32; j++) {
        int c = j * 8 + ct;
        s0[j] += rpb0[c] + mk0[c];
        s1[j] += rpb1[c] + mk1[c];
    }

    float mx0 = -1e30f, mx1 = -1e30f;
#pragma unroll
    for (int j = 0; j < 32; j++) { mx0 = fmaxf(mx0, s0[j]); mx1 = fmaxf(mx1, s1[j]); }
#pragma unroll
    for (int w = 1; w <= 4; w <<= 1) {
        mx0 = fmaxf(mx0, __shfl_xor_sync(0xffffffffu, mx0, w));
        mx1 = fmaxf(mx1, __shfl_xor_sync(0xffffffffu, mx1, w));
    }
    float sum0 = 0.f, sum1 = 0.f;
#pragma unroll
    for (int j = 0; j < 32; j += 2) {
        __half2 h0 = h2exp(__floats2half2_rn(s0[j] - mx0, s0[j + 1] - mx0));
        __half2 h1 = h2exp(__floats2half2_rn(s1[j] - mx1, s1[j + 1] - mx1));
        float2 e0 = __half22float2(h0);
        float2 e1 = __half22float2(h1);
        s0[j] = e0.x; s0[j + 1] = e0.y; sum0 += e0.x + e0.y;
        s1[j] = e1.x; s1[j + 1] = e1.y; sum1 += e1.x + e1.y;
    }
#pragma unroll
    for (int w = 1; w <= 4; w <<= 1) {
        sum0 += __shfl_xor_sync(0xffffffffu, sum0, w);
        sum1 += __shfl_xor_sync(0xffffffffu, sum1, w);
    }
    float inv0 = 1.0f / sum0, inv1 = 1.0f / sum1;

    float o0[32], o1[32];
#pragma unroll
    for (int d = 0; d < 32; d++) { o0[d] = 0.f; o1[d] = 0.f; }
#pragma unroll
    for (int j = 0; j < 32; j++) {
        int c = j * 8 + ct;
        float p0 = s0[j], p1 = s1[j];
#pragma unroll
        for (int dd = 0; dd < 8; dd++) {
            float4 v4 = *(const float4*)(Vs + c * AST + dd * 4);
            o0[dd * 4 + 0] += p0 * v4.x; o0[dd * 4 + 1] += p0 * v4.y;
            o0[dd * 4 + 2] += p0 * v4.z; o0[dd * 4 + 3] += p0 * v4.w;
            o1[dd * 4 + 0] += p1 * v4.x; o1[dd * 4 + 1] += p1 * v4.y;
            o1[dd * 4 + 2] += p1 * v4.z; o1[dd * 4 + 3] += p1 * v4.w;
        }
    }

    float a0[16], a1[16];
#pragma unroll
    for (int i = 0; i < 16; i++) {
        float keep0 = (ct & 4) ? o0[16 + i] : o0[i];
        float give0 = (ct & 4) ? o0[i] : o0[16 + i];
        a0[i] = keep0 + __shfl_xor_sync(0xffffffffu, give0, 4);
        float keep1 = (ct & 4) ? o1[16 + i] : o1[i];
        float give1 = (ct & 4) ? o1[i] : o1[16 + i];
        a1[i] = keep1 + __shfl_xor_sync(0xffffffffu, give1, 4);
    }
    float c0[8], c1[8];
#pragma unroll
    for (int i = 0; i < 8; i++) {
        float keep0 = (ct & 2) ? a0[8 + i] : a0[i];
        float give0 = (ct & 2) ? a0[i] : a0[8 + i];
        c0[i] = keep0 + __shfl_xor_sync(0xffffffffu, give0, 2);
        float keep1 = (ct & 2) ? a1[8 + i] : a1[i];
        float give1 = (ct & 2) ? a1[i] : a1[8 + i];
        c1[i] = keep1 + __shfl_xor_sync(0xffffffffu, give1, 2);
    }
    float f0[4], f1[4];
#pragma unroll
    for (int i = 0; i < 4; i++) {
        float keep0 = (ct & 1) ? c0[4 + i] : c0[i];
        float give0 = (ct & 1) ? c0[i] : c0[4 + i];
        f0[i] = keep0 + __shfl_xor_sync(0xffffffffu, give0, 1);
        float keep1 = (ct & 1) ? c1[4 + i] : c1[i];
        float give1 = (ct & 1) ? c1[i] : c1[4 + i];
        f1[i] = keep1 + __shfl_xor_sync(0xffffffffu, give1, 1);
    }
    float4 w0, w1;
    w0.x = f0[0] * inv0; w0.y = f0[1] * inv0; w0.z = f0[2] * inv0; w0.w = f0[3] * inv0;
    w1.x = f1[0] * inv1; w1.y = f1[1] * inv1; w1.z = f1[2] * inv1; w1.w = f1[3] * inv1;
    *(float4*)(g_x + (size_t)(b * NTOK + r0 + ra) * DIMC + h * HD + ct * 4) = w0;
    *(float4*)(g_x + (size_t)(b * NTOK + r0 + rb) * DIMC + h * HD + ct * 4) = w1;
}

// ---------------- launch ----------------
extern "C" void kernel_launch(void* const* d_in, const int* in_sizes, int n_in,
                              void* d_out, int out_size) {
    const float* q      = (const float*)d_in[0];
    const float* k      = (const float*)d_in[1];
    const float* mask   = (const float*)d_in[2];
    const float* q_w    = (const float*)d_in[3];
    const float* q_b    = (const float*)d_in[4];
    const float* kv_w   = (const float*)d_in[5];
    const float* kv_b   = (const float*)d_in[6];
    const float* proj_w = (const float*)d_in[7];
    const float* proj_b = (const float*)d_in[8];
    const float* pp_w   = (const float*)d_in[9];
    const float* pp_b   = (const float*)d_in[10];
    const float* ln1_g  = (const float*)d_in[11];
    const float* ln1_b  = (const float*)d_in[12];
    const float* l1_w   = (const float*)d_in[13];
    const float* l1_b   = (const float*)d_in[14];
    const float* ln2_g  = (const float*)d_in[15];
    const float* ln2_b  = (const float*)d_in[16];
    const float* l2_w   = (const float*)d_in[17];
    const float* l2_b   = (const float*)d_in[18];
    const float* ln3_g  = (const float*)d_in[19];
    const float* ln3_b  = (const float*)d_in[20];
    const float* l3_w   = (const float*)d_in[21];
    const float* l3_b   = (const float*)d_in[22];
    (void)in_sizes; (void)n_in; (void)out_size;

    float *qh, *kv, *x;
    cudaGetSymbolAddress((void**)&qh, g_qh);
    cudaGetSymbolAddress((void**)&kv, g_kv);
    cudaGetSymbolAddress((void**)&x,  g_x);

    int gsmem = 2 * GSTAGE * (int)sizeof(uint32_t);            // 81920
    int asmem = (64 + 2 * NTOK) * AST * (int)sizeof(float);    // 82944
    static int attr_done = 0;
    if (!attr_done) {
        cudaFuncSetAttribute(gemm_bf16, cudaFuncAttributeMaxDynamicSharedMemorySize, gsmem);
        cudaFuncSetAttribute(attn_kernel, cudaFuncAttributeMaxDynamicSharedMemorySize, asmem);
        attr_done = 1;
    }

    pos_mlp_kernel<<<4, 256>>>(pp_w, pp_b, ln1_g, ln1_b, l1_w, l1_b,
                               ln2_g, ln2_b, l2_w, l2_b, ln3_g, ln3_b, l3_w, l3_b);
    rpb_fill_kernel<<<NHEAD * NTOK * NTOK / 256, 256>>>();

    const int M = BATCH * NTOK;   // 65536
    gemm_bf16<<<dim3(DIMC / 128, M / 128), 256, gsmem>>>(q, q_w, q_b, qh, M, DIMC, DIMC);
    gemm_bf16<<<dim3(2 * DIMC / 128, M / 128), 256, gsmem>>>(k, kv_w, kv_b, kv, M, 2 * DIMC, DIMC);

    attn_kernel<<<dim3(4, NHEAD, BATCH), 256, asmem>>>(mask);

    gemm_bf16<<<dim3(DIMC / 128, M / 128), 256, gsmem>>>(x, proj_w, proj_b, (float*)d_out, M, DIMC, DIMC);
}

// round 5
// speedup vs baseline: 2.4430x; 1.0838x over previous
#include <cuda_runtime.h>
#include <cuda_bf16.h>
#include <cuda_fp16.h>
#include <cstdint>
#include <cstddef>

// ---------------- problem constants ----------------
#define NHEAD 8
#define HD 32
#define NTOK 256
#define BATCH 256
#define DIMC 256
#define NGROUP 64
#define PD 16
#define LREL 961   // (2*16-1)^2

// ---------------- device scratch ----------------
__device__ float g_qh[BATCH * NTOK * DIMC];
__device__ float g_kv[BATCH * NTOK * 2 * DIMC];
__device__ float g_x [BATCH * NTOK * DIMC];
__device__ float g_pos[LREL * NHEAD];
__device__ float g_rpb[NHEAD * NTOK * NTOK];

// ---------------- f32x2 packed helpers ----------------
__device__ __forceinline__ void fma2(unsigned long long& d, unsigned long long a, unsigned long long b) {
    asm("fma.rn.f32x2 %0, %1, %2, %0;" : "+l"(d) : "l"(a), "l"(b));
}
__device__ __forceinline__ unsigned long long add2(unsigned long long a, unsigned long long b) {
    unsigned long long d;
    asm("add.rn.f32x2 %0, %1, %2;" : "=l"(d) : "l"(a), "l"(b));
    return d;
}
__device__ __forceinline__ unsigned long long pack2(float x, float y) {
    unsigned long long d;
    asm("mov.b64 %0, {%1, %2};" : "=l"(d) : "f"(x), "f"(y));
    return d;
}
__device__ __forceinline__ float2 unpack2(unsigned long long v) {
    float2 f;
    asm("mov.b64 {%0, %1}, %2;" : "=f"(f.x), "=f"(f.y) : "l"(v));
    return f;
}

// ---------------- mma helpers ----------------
__device__ __forceinline__ void pack_bf16_pair(float x, float y, uint32_t& hi, uint32_t& lo) {
    __nv_bfloat16 hx = __float2bfloat16_rn(x);
    __nv_bfloat16 hy = __float2bfloat16_rn(y);
    float rx = x - __bfloat162float(hx);
    float ry = y - __bfloat162float(hy);
    __nv_bfloat16 lx = __float2bfloat16_rn(rx);
    __nv_bfloat16 ly = __float2bfloat16_rn(ry);
    hi = ((uint32_t)__bfloat16_as_ushort(hy) << 16) | (uint32_t)__bfloat16_as_ushort(hx);
    lo = ((uint32_t)__bfloat16_as_ushort(ly) << 16) | (uint32_t)__bfloat16_as_ushort(lx);
}
__device__ __forceinline__ void mma_bf16(float* d, const uint32_t* a, const uint32_t* b) {
    asm volatile("mma.sync.aligned.m16n8k16.row.col.f32.bf16.bf16.f32 "
        "{%0,%1,%2,%3}, {%4,%5,%6,%7}, {%8,%9}, {%0,%1,%2,%3};"
        : "+f"(d[0]), "+f"(d[1]), "+f"(d[2]), "+f"(d[3])
        : "r"(a[0]), "r"(a[1]), "r"(a[2]), "r"(a[3]), "r"(b[0]), "r"(b[1]));
}

// ---------------- pos-bias MLP ----------------
__device__ __forceinline__ void ln16(float* x, const float* g, const float* b) {
    float m = 0.f;
#pragma unroll
    for (int i = 0; i < PD; i++) m += x[i];
    m *= (1.0f / PD);
    float v = 0.f;
#pragma unroll
    for (int i = 0; i < PD; i++) { float d = x[i] - m; v += d * d; }
    v *= (1.0f / PD);
    float inv = rsqrtf(v + 1e-5f);
#pragma unroll
    for (int i = 0; i < PD; i++) x[i] = (x[i] - m) * inv * g[i] + b[i];
}

__global__ void pos_mlp_kernel(const float* __restrict__ pp_w, const float* __restrict__ pp_b,
                               const float* __restrict__ ln1_g, const float* __restrict__ ln1_b,
                               const float* __restrict__ l1_w,  const float* __restrict__ l1_b,
                               const float* __restrict__ ln2_g, const float* __restrict__ ln2_b,
                               const float* __restrict__ l2_w,  const float* __restrict__ l2_b,
                               const float* __restrict__ ln3_g, const float* __restrict__ ln3_b,
                               const float* __restrict__ l3_w,  const float* __restrict__ l3_b) {
    int p = blockIdx.x * blockDim.x + threadIdx.x;
    if (p >= LREL) return;
    float b0 = (float)(p / 31 - 15);
    float b1 = (float)(p % 31 - 15);
    float x[PD], y[PD];
#pragma unroll
    for (int o = 0; o < PD; o++) x[o] = b0 * pp_w[o * 2 + 0] + b1 * pp_w[o * 2 + 1] + pp_b[o];
    ln16(x, ln1_g, ln1_b);
#pragma unroll
    for (int o = 0; o < PD; o++) {
        float s = l1_b[o];
#pragma unroll
        for (int i = 0; i < PD; i++) s += fmaxf(x[i], 0.f) * l1_w[o * PD + i];
        y[o] = s;
    }
#pragma unroll
    for (int o = 0; o < PD; o++) x[o] = y[o];
    ln16(x, ln2_g, ln2_b);
#pragma unroll
    for (int o = 0; o < PD; o++) {
        float s = l2_b[o];
#pragma unroll
        for (int i = 0; i < PD; i++) s += fmaxf(x[i], 0.f) * l2_w[o * PD + i];
        y[o] = s;
    }
#pragma unroll
    for (int o = 0; o < PD; o++) x[o] = y[o];
    ln16(x, ln3_g, ln3_b);
#pragma unroll
    for (int h = 0; h < NHEAD; h++) {
        float s = l3_b[h];
#pragma unroll
        for (int i = 0; i < PD; i++) s += fmaxf(x[i], 0.f) * l3_w[h * PD + i];
        g_pos[p * NHEAD + h] = s;
    }
}

__global__ void rpb_fill_kernel() {
    int i = blockIdx.x * 256 + threadIdx.x;
    int h = i >> 16;
    int rem = i & 65535;
    int n = rem >> 8;
    int m = rem & 255;
    int di = (n >> 4) - (m >> 4) + 15;
    int dj = (n & 15) - (m & 15) + 15;
    g_rpb[i] = g_pos[(di * 31 + dj) * NHEAD + h];
}

// ---------------- bf16-split mma.sync GEMM (unchanged from round 4) ----------------
#define GPAD 20
#define GTILE (128 * GPAD)
#define GSTAGE (4 * GTILE)
__global__ __launch_bounds__(256)
void gemm_bf16(const float* __restrict__ A, const float* __restrict__ W,
               const float* __restrict__ bias, float* __restrict__ C,
               int M, int Ncols, int K) {
    extern __shared__ uint32_t gsm[];
    int tid = threadIdx.x, lane = tid & 31, wid = tid >> 5;
    int m0 = blockIdx.y * 128, n0 = blockIdx.x * 128;
    int wm = (wid >> 2) * 64, wn = (wid & 3) * 32;
    int g = lane >> 2, tg = lane & 3;

    float acc[4][4][4];
#pragma unroll
    for (int a = 0; a < 4; a++)
#pragma unroll
        for (int bq = 0; bq < 4; bq++)
#pragma unroll
            for (int c = 0; c < 4; c++) acc[a][bq][c] = 0.f;

    int lrow = tid >> 3;
    int lc4 = (tid & 7) * 4;
    int lp = lc4 >> 1;

    {
        uint32_t* sAhi = gsm;             uint32_t* sAlo = gsm + GTILE;
        uint32_t* sBhi = gsm + 2 * GTILE; uint32_t* sBlo = gsm + 3 * GTILE;
#pragma unroll
        for (int it = 0; it < 4; it++) {
            int row = it * 32 + lrow;
            float4 a4 = *(const float4*)(A + (size_t)(m0 + row) * K + lc4);
            float4 b4 = *(const float4*)(W + (size_t)(n0 + row) * K + lc4);
            uint32_t h0, l0, h1, l1;
            pack_bf16_pair(a4.x, a4.y, h0, l0); pack_bf16_pair(a4.z, a4.w, h1, l1);
            sAhi[row * GPAD + lp] = h0; sAhi[row * GPAD + lp + 1] = h1;
            sAlo[row * GPAD + lp] = l0; sAlo[row * GPAD + lp + 1] = l1;
            pack_bf16_pair(b4.x, b4.y, h0, l0); pack_bf16_pair(b4.z, b4.w, h1, l1);
            sBhi[row * GPAD + lp] = h0; sBhi[row * GPAD + lp + 1] = h1;
            sBlo[row * GPAD + lp] = l0; sBlo[row * GPAD + lp + 1] = l1;
        }
    }
    __syncthreads();

    int nch = K >> 5;
    for (int kc = 0; kc < nch; kc++) {
        int s = kc & 1;
        if (kc + 1 < nch) {
            uint32_t* st = gsm + (s ^ 1) * GSTAGE;
            uint32_t* sAhi = st;             uint32_t* sAlo = st + GTILE;
            uint32_t* sBhi = st + 2 * GTILE; uint32_t* sBlo = st + 3 * GTILE;
            const float* Ap = A + (kc + 1) * 32;
            const float* Wp = W + (kc + 1) * 32;
#pragma unroll
            for (int it = 0; it < 4; it++) {
                int row = it * 32 + lrow;
                float4 a4 = *(const float4*)(Ap + (size_t)(m0 + row) * K + lc4);
                float4 b4 = *(const float4*)(Wp + (size_t)(n0 + row) * K + lc4);
                uint32_t h0, l0, h1, l1;
                pack_bf16_pair(a4.x, a4.y, h0, l0); pack_bf16_pair(a4.z, a4.w, h1, l1);
                sAhi[row * GPAD + lp] = h0; sAhi[row * GPAD + lp + 1] = h1;
                sAlo[row * GPAD + lp] = l0; sAlo[row * GPAD + lp + 1] = l1;
                pack_bf16_pair(b4.x, b4.y, h0, l0); pack_bf16_pair(b4.z, b4.w, h1, l1);
                sBhi[row * GPAD + lp] = h0; sBhi[row * GPAD + lp + 1] = h1;
                sBlo[row * GPAD + lp] = l0; sBlo[row * GPAD + lp + 1] = l1;
            }
        }
        uint32_t* st = gsm + s * GSTAGE;
        uint32_t* sAhi = st;             uint32_t* sAlo = st + GTILE;
        uint32_t* sBhi = st + 2 * GTILE; uint32_t* sBlo = st + 3 * GTILE;
#pragma unroll
        for (int ks = 0; ks < 2; ks++) {
            int pc = ks * 8 + tg;
            uint32_t ahi[4][4], alo[4][4], bhi[4][2], blo[4][2];
#pragma unroll
            for (int mt = 0; mt < 4; mt++) {
                int base = (wm + mt * 16 + g) * GPAD + pc;
                ahi[mt][0] = sAhi[base];              alo[mt][0] = sAlo[base];
                ahi[mt][1] = sAhi[base + 8 * GPAD];   alo[mt][1] = sAlo[base + 8 * GPAD];
                ahi[mt][2] = sAhi[base + 4];          alo[mt][2] = sAlo[base + 4];
                ahi[mt][3] = sAhi[base + 8 * GPAD + 4]; alo[mt][3] = sAlo[base + 8 * GPAD + 4];
            }
#pragma unroll
            for (int nt = 0; nt < 4; nt++) {
                int base = (wn + nt * 8 + g) * GPAD + pc;
                bhi[nt][0] = sBhi[base]; bhi[nt][1] = sBhi[base + 4];
                blo[nt][0] = sBlo[base]; blo[nt][1] = sBlo[base + 4];
            }
#pragma unroll
            for (int mt = 0; mt < 4; mt++)
#pragma unroll
                for (int nt = 0; nt < 4; nt++) {
                    mma_bf16(acc[mt][nt], ahi[mt], bhi[nt]);
                    mma_bf16(acc[mt][nt], ahi[mt], blo[nt]);
                    mma_bf16(acc[mt][nt], alo[mt], bhi[nt]);
                }
        }
        __syncthreads();
    }

#pragma unroll
    for (int mt = 0; mt < 4; mt++) {
        int r0 = m0 + wm + mt * 16 + g;
#pragma unroll
        for (int nt = 0; nt < 4; nt++) {
            int col = n0 + wn + nt * 8 + 2 * tg;
            float bb0 = bias[col], bb1 = bias[col + 1];
            float2 v0, v1;
            v0.x = acc[mt][nt][0] + bb0; v0.y = acc[mt][nt][1] + bb1;
            v1.x = acc[mt][nt][2] + bb0; v1.y = acc[mt][nt][3] + bb1;
            *(float2*)(C + (size_t)r0 * Ncols + col) = v0;
            *(float2*)(C + (size_t)(r0 + 8) * Ncols + col) = v1;
        }
    }
}

// ---------------- fused attention (4 rows/thread, f32x2 packed) ----------------
// grid (4, 8, 256), 256 threads. rg = tid>>4 owns rows 4rg..4rg+3; ct = tid&15
// owns cols c = j*16 + ct (j<16). Scores accumulated as (even-d, odd-d) f32x2
// partial pairs; output accumulated as d-pair f32x2.
#define AST 36
__global__ __launch_bounds__(256, 1)
void attn_kernel(const float* __restrict__ mask) {
    extern __shared__ float sm[];
    float* Qs = sm;                    // 64 * 36
    float* Ks = sm + 64 * AST;         // 256 * 36
    float* Vs = Ks + 256 * AST;        // 256 * 36
    int tid = threadIdx.x;
    int r0 = blockIdx.x * 64, h = blockIdx.y, b = blockIdx.z;
    int rg = tid >> 4, ct = tid & 15;

    {
        int dd4 = (tid & 7) * 4;
        const float scale = 0.17677669529663687f;   // 32^-0.5
#pragma unroll
        for (int it = 0; it < 8; it++) {
            int nn = it * 32 + (tid >> 3);
            const float* src = g_kv + (size_t)(b * NTOK + nn) * (2 * DIMC) + h * HD + dd4;
            *(float4*)(Ks + nn * AST + dd4) = *(const float4*)src;
            *(float4*)(Vs + nn * AST + dd4) = *(const float4*)(src + DIMC);
        }
#pragma unroll
        for (int it = 0; it < 2; it++) {
            int rr = it * 32 + (tid >> 3);
            float4 qv = *(const float4*)(g_qh + (size_t)(b * NTOK + r0 + rr) * DIMC + h * HD + dd4);
            qv.x *= scale; qv.y *= scale; qv.z *= scale; qv.w *= scale;
            *(float4*)(Qs + rr * AST + dd4) = qv;
        }
    }
    __syncthreads();

    int rbase = rg * 4;

    // ---- QK^T: s[r][j] holds (sum_even_d, sum_odd_d) ----
    unsigned long long s[4][16];
#pragma unroll
    for (int r = 0; r < 4; r++)
#pragma unroll
        for (int j = 0; j < 16; j++) s[r][j] = 0ull;

#pragma unroll
    for (int kq = 0; kq < 8; kq++) {
        ulonglong2 q2[4];
#pragma unroll
        for (int r = 0; r < 4; r++)
            q2[r] = *(const ulonglong2*)(Qs + (rbase + r) * AST + kq * 4);
#pragma unroll
        for (int j = 0; j < 16; j++) {
            ulonglong2 k2 = *(const ulonglong2*)(Ks + (j * 16 + ct) * AST + kq * 4);
#pragma unroll
            for (int r = 0; r < 4; r++) {
                fma2(s[r][j], k2.x, q2[r].x);
                fma2(s[r][j], k2.y, q2[r].y);
            }
        }
    }

    // ---- horizontal add + rpb + mask + softmax ----
    float p[4][16];
    float inv[4];
    const float* rpbB = g_rpb + ((size_t)h * NTOK + (r0 + rbase)) * NTOK;
    const float* mkB  = mask + ((size_t)(b & (NGROUP - 1)) * NTOK + (r0 + rbase)) * NTOK;
#pragma unroll
    for (int r = 0; r < 4; r++) {
        const float* rpbR = rpbB + r * NTOK;
        const float* mkR  = mkB + r * NTOK;
        float mx = -1e30f;
#pragma unroll
        for (int j = 0; j < 16; j++) {
            float2 sv = unpack2(s[r][j]);
            float sc = sv.x + sv.y + rpbR[j * 16 + ct] + mkR[j * 16 + ct];
            p[r][j] = sc;
            mx = fmaxf(mx, sc);
        }
#pragma unroll
        for (int w = 1; w <= 8; w <<= 1)
            mx = fmaxf(mx, __shfl_xor_sync(0xffffffffu, mx, w));
        float sum = 0.f;
#pragma unroll
        for (int j = 0; j < 16; j += 2) {
            __half2 hx = h2exp(__floats2half2_rn(p[r][j] - mx, p[r][j + 1] - mx));
            float2 e = __half22float2(hx);
            p[r][j] = e.x; p[r][j + 1] = e.y;
            sum += e.x + e.y;
        }
#pragma unroll
        for (int w = 1; w <= 8; w <<= 1)
            sum += __shfl_xor_sync(0xffffffffu, sum, w);
        inv[r] = 1.0f / sum;
    }

    // ---- P @ V: o[r][dp] holds dims (2dp, 2dp+1) ----
    unsigned long long o[4][16];
#pragma unroll
    for (int r = 0; r < 4; r++)
#pragma unroll
        for (int dp = 0; dp < 16; dp++) o[r][dp] = 0ull;

#pragma unroll
    for (int j = 0; j < 16; j++) {
        int c = j * 16 + ct;
        unsigned long long pp[4];
#pragma unroll
        for (int r = 0; r < 4; r++) pp[r] = pack2(p[r][j], p[r][j]);
        const float* vr = Vs + c * AST;
#pragma unroll
        for (int vq = 0; vq < 8; vq++) {
            ulonglong2 v2 = *(const ulonglong2*)(vr + vq * 4);
#pragma unroll
            for (int r = 0; r < 4; r++) {
                fma2(o[r][2 * vq + 0], v2.x, pp[r]);
                fma2(o[r][2 * vq + 1], v2.y, pp[r]);
            }
        }
    }

    // ---- reduce over 16 ct lanes; lane ct keeps d-pair ct ----
#pragma unroll
    for (int r = 0; r < 4; r++) {
        unsigned long long t8[8];
#pragma unroll
        for (int i = 0; i < 8; i++) {
            unsigned long long keep = (ct & 8) ? o[r][8 + i] : o[r][i];
            unsigned long long give = (ct & 8) ? o[r][i] : o[r][8 + i];
            t8[i] = add2(keep, __shfl_xor_sync(0xffffffffu, give, 8));
        }
        unsigned long long t4[4];
#pragma unroll
        for (int i = 0; i < 4; i++) {
            unsigned long long keep = (ct & 4) ? t8[4 + i] : t8[i];
            unsigned long long give = (ct & 4) ? t8[i] : t8[4 + i];
            t4[i] = add2(keep, __shfl_xor_sync(0xffffffffu, give, 4));
        }
        unsigned long long t2[2];
#pragma unroll
        for (int i = 0; i < 2; i++) {
            unsigned long long keep = (ct & 2) ? t4[2 + i] : t4[i];
            unsigned long long give = (ct & 2) ? t4[i] : t4[2 + i];
            t2[i] = add2(keep, __shfl_xor_sync(0xffffffffu, give, 2));
        }
        unsigned long long keep = (ct & 1) ? t2[1] : t2[0];
        unsigned long long give = (ct & 1) ? t2[0] : t2[1];
        unsigned long long fin = add2(keep, __shfl_xor_sync(0xffffffffu, give, 1));
        float2 fo = unpack2(fin);
        fo.x *= inv[r]; fo.y *= inv[r];
        *(float2*)(g_x + (size_t)(b * NTOK + r0 + rbase + r) * DIMC + h * HD + ct * 2) = fo;
    }
}

// ---------------- launch ----------------
extern "C" void kernel_launch(void* const* d_in, const int* in_sizes, int n_in,
                              void* d_out, int out_size) {
    const float* q      = (const float*)d_in[0];
    const float* k      = (const float*)d_in[1];
    const float* mask   = (const float*)d_in[2];
    const float* q_w    = (const float*)d_in[3];
    const float* q_b    = (const float*)d_in[4];
    const float* kv_w   = (const float*)d_in[5];
    const float* kv_b   = (const float*)d_in[6];
    const float* proj_w = (const float*)d_in[7];
    const float* proj_b = (const float*)d_in[8];
    const float* pp_w   = (const float*)d_in[9];
    const float* pp_b   = (const float*)d_in[10];
    const float* ln1_g  = (const float*)d_in[11];
    const float* ln1_b  = (const float*)d_in[12];
    const float* l1_w   = (const float*)d_in[13];
    const float* l1_b   = (const float*)d_in[14];
    const float* ln2_g  = (const float*)d_in[15];
    const float* ln2_b  = (const float*)d_in[16];
    const float* l2_w   = (const float*)d_in[17];
    const float* l2_b   = (const float*)d_in[18];
    const float* ln3_g  = (const float*)d_in[19];
    const float* ln3_b  = (const float*)d_in[20];
    const float* l3_w   = (const float*)d_in[21];
    const float* l3_b   = (const float*)d_in[22];
    (void)in_sizes; (void)n_in; (void)out_size;

    float *qh, *kv, *x;
    cudaGetSymbolAddress((void**)&qh, g_qh);
    cudaGetSymbolAddress((void**)&kv, g_kv);
    cudaGetSymbolAddress((void**)&x,  g_x);

    int gsmem = 2 * GSTAGE * (int)sizeof(uint32_t);            // 81920
    int asmem = (64 + 2 * NTOK) * AST * (int)sizeof(float);    // 82944
    static int attr_done = 0;
    if (!attr_done) {
        cudaFuncSetAttribute(gemm_bf16, cudaFuncAttributeMaxDynamicSharedMemorySize, gsmem);
        cudaFuncSetAttribute(attn_kernel, cudaFuncAttributeMaxDynamicSharedMemorySize, asmem);
        attr_done = 1;
    }

    pos_mlp_kernel<<<4, 256>>>(pp_w, pp_b, ln1_g, ln1_b, l1_w, l1_b,
                               ln2_g, ln2_b, l2_w, l2_b, ln3_g, ln3_b, l3_w, l3_b);
    rpb_fill_kernel<<<NHEAD * NTOK * NTOK / 256, 256>>>();

    const int M = BATCH * NTOK;   // 65536
    gemm_bf16<<<dim3(DIMC / 128, M / 128), 256, gsmem>>>(q, q_w, q_b, qh, M, DIMC, DIMC);
    gemm_bf16<<<dim3(2 * DIMC / 128, M / 128), 256, gsmem>>>(k, kv_w, kv_b, kv, M, 2 * DIMC, DIMC);

    attn_kernel<<<dim3(4, NHEAD, BATCH), 256, asmem>>>(mask);

    gemm_bf16<<<dim3(DIMC / 128, M / 128), 256, gsmem>>>(x, proj_w, proj_b, (float*)d_out, M, DIMC, DIMC);
}

// round 6
// speedup vs baseline: 3.2933x; 1.3480x over previous
#include <cuda_runtime.h>
#include <cuda_bf16.h>
#include <cuda_fp16.h>
#include <cstdint>
#include <cstddef>

// ---------------- problem constants ----------------
#define NHEAD 8
#define HD 32
#define NTOK 256
#define BATCH 256
#define DIMC 256
#define NGROUP 64
#define PD 16
#define LREL 961   // (2*16-1)^2

// ---------------- device scratch ----------------
__device__ float g_qh[BATCH * NTOK * DIMC];
__device__ float g_kv[BATCH * NTOK * 2 * DIMC];
__device__ float g_x [BATCH * NTOK * DIMC];
__device__ float g_pos[LREL * NHEAD];
__device__ float g_rpb[NHEAD * NTOK * NTOK];

// ---------------- mma helpers ----------------
__device__ __forceinline__ void pack_bf16_pair(float x, float y, uint32_t& hi, uint32_t& lo) {
    __nv_bfloat16 hx = __float2bfloat16_rn(x);
    __nv_bfloat16 hy = __float2bfloat16_rn(y);
    float rx = x - __bfloat162float(hx);
    float ry = y - __bfloat162float(hy);
    __nv_bfloat16 lx = __float2bfloat16_rn(rx);
    __nv_bfloat16 ly = __float2bfloat16_rn(ry);
    hi = ((uint32_t)__bfloat16_as_ushort(hy) << 16) | (uint32_t)__bfloat16_as_ushort(hx);
    lo = ((uint32_t)__bfloat16_as_ushort(ly) << 16) | (uint32_t)__bfloat16_as_ushort(lx);
}
__device__ __forceinline__ void mma_bf16(float* d, const uint32_t* a, const uint32_t* b) {
    asm volatile("mma.sync.aligned.m16n8k16.row.col.f32.bf16.bf16.f32 "
        "{%0,%1,%2,%3}, {%4,%5,%6,%7}, {%8,%9}, {%0,%1,%2,%3};"
        : "+f"(d[0]), "+f"(d[1]), "+f"(d[2]), "+f"(d[3])
        : "r"(a[0]), "r"(a[1]), "r"(a[2]), "r"(a[3]), "r"(b[0]), "r"(b[1]));
}
__device__ __forceinline__ void mma_f16(float* d, const uint32_t* a, const uint32_t* b) {
    asm volatile("mma.sync.aligned.m16n8k16.row.col.f32.f16.f16.f32 "
        "{%0,%1,%2,%3}, {%4,%5,%6,%7}, {%8,%9}, {%0,%1,%2,%3};"
        : "+f"(d[0]), "+f"(d[1]), "+f"(d[2]), "+f"(d[3])
        : "r"(a[0]), "r"(a[1]), "r"(a[2]), "r"(a[3]), "r"(b[0]), "r"(b[1]));
}

// ---------------- pos-bias MLP ----------------
__device__ __forceinline__ void ln16(float* x, const float* g, const float* b) {
    float m = 0.f;
#pragma unroll
    for (int i = 0; i < PD; i++) m += x[i];
    m *= (1.0f / PD);
    float v = 0.f;
#pragma unroll
    for (int i = 0; i < PD; i++) { float d = x[i] - m; v += d * d; }
    v *= (1.0f / PD);
    float inv = rsqrtf(v + 1e-5f);
#pragma unroll
    for (int i = 0; i < PD; i++) x[i] = (x[i] - m) * inv * g[i] + b[i];
}

__global__ void pos_mlp_kernel(const float* __restrict__ pp_w, const float* __restrict__ pp_b,
                               const float* __restrict__ ln1_g, const float* __restrict__ ln1_b,
                               const float* __restrict__ l1_w,  const float* __restrict__ l1_b,
                               const float* __restrict__ ln2_g, const float* __restrict__ ln2_b,
                               const float* __restrict__ l2_w,  const float* __restrict__ l2_b,
                               const float* __restrict__ ln3_g, const float* __restrict__ ln3_b,
                               const float* __restrict__ l3_w,  const float* __restrict__ l3_b) {
    int p = blockIdx.x * blockDim.x + threadIdx.x;
    if (p >= LREL) return;
    float b0 = (float)(p / 31 - 15);
    float b1 = (float)(p % 31 - 15);
    float x[PD], y[PD];
#pragma unroll
    for (int o = 0; o < PD; o++) x[o] = b0 * pp_w[o * 2 + 0] + b1 * pp_w[o * 2 + 1] + pp_b[o];
    ln16(x, ln1_g, ln1_b);
#pragma unroll
    for (int o = 0; o < PD; o++) {
        float s = l1_b[o];
#pragma unroll
        for (int i = 0; i < PD; i++) s += fmaxf(x[i], 0.f) * l1_w[o * PD + i];
        y[o] = s;
    }
#pragma unroll
    for (int o = 0; o < PD; o++) x[o] = y[o];
    ln16(x, ln2_g, ln2_b);
#pragma unroll
    for (int o = 0; o < PD; o++) {
        float s = l2_b[o];
#pragma unroll
        for (int i = 0; i < PD; i++) s += fmaxf(x[i], 0.f) * l2_w[o * PD + i];
        y[o] = s;
    }
#pragma unroll
    for (int o = 0; o < PD; o++) x[o] = y[o];
    ln16(x, ln3_g, ln3_b);
#pragma unroll
    for (int h = 0; h < NHEAD; h++) {
        float s = l3_b[h];
#pragma unroll
        for (int i = 0; i < PD; i++) s += fmaxf(x[i], 0.f) * l3_w[h * PD + i];
        g_pos[p * NHEAD + h] = s;
    }
}

__global__ void rpb_fill_kernel() {
    int i = blockIdx.x * 256 + threadIdx.x;
    int h = i >> 16;
    int rem = i & 65535;
    int n = rem >> 8;
    int m = rem & 255;
    int di = (n >> 4) - (m >> 4) + 15;
    int dj = (n & 15) - (m & 15) + 15;
    g_rpb[i] = g_pos[(di * 31 + dj) * NHEAD + h];
}

// ---------------- bf16-split mma.sync GEMM (unchanged) ----------------
#define GPAD 20
#define GTILE (128 * GPAD)
#define GSTAGE (4 * GTILE)
__global__ __launch_bounds__(256)
void gemm_bf16(const float* __restrict__ A, const float* __restrict__ W,
               const float* __restrict__ bias, float* __restrict__ C,
               int M, int Ncols, int K) {
    extern __shared__ uint32_t gsm[];
    int tid = threadIdx.x, lane = tid & 31, wid = tid >> 5;
    int m0 = blockIdx.y * 128, n0 = blockIdx.x * 128;
    int wm = (wid >> 2) * 64, wn = (wid & 3) * 32;
    int g = lane >> 2, tg = lane & 3;

    float acc[4][4][4];
#pragma unroll
    for (int a = 0; a < 4; a++)
#pragma unroll
        for (int bq = 0; bq < 4; bq++)
#pragma unroll
            for (int c = 0; c < 4; c++) acc[a][bq][c] = 0.f;

    int lrow = tid >> 3;
    int lc4 = (tid & 7) * 4;
    int lp = lc4 >> 1;

    {
        uint32_t* sAhi = gsm;             uint32_t* sAlo = gsm + GTILE;
        uint32_t* sBhi = gsm + 2 * GTILE; uint32_t* sBlo = gsm + 3 * GTILE;
#pragma unroll
        for (int it = 0; it < 4; it++) {
            int row = it * 32 + lrow;
            float4 a4 = *(const float4*)(A + (size_t)(m0 + row) * K + lc4);
            float4 b4 = *(const float4*)(W + (size_t)(n0 + row) * K + lc4);
            uint32_t h0, l0, h1, l1;
            pack_bf16_pair(a4.x, a4.y, h0, l0); pack_bf16_pair(a4.z, a4.w, h1, l1);
            sAhi[row * GPAD + lp] = h0; sAhi[row * GPAD + lp + 1] = h1;
            sAlo[row * GPAD + lp] = l0; sAlo[row * GPAD + lp + 1] = l1;
            pack_bf16_pair(b4.x, b4.y, h0, l0); pack_bf16_pair(b4.z, b4.w, h1, l1);
            sBhi[row * GPAD + lp] = h0; sBhi[row * GPAD + lp + 1] = h1;
            sBlo[row * GPAD + lp] = l0; sBlo[row * GPAD + lp + 1] = l1;
        }
    }
    __syncthreads();

    int nch = K >> 5;
    for (int kc = 0; kc < nch; kc++) {
        int s = kc & 1;
        if (kc + 1 < nch) {
            uint32_t* st = gsm + (s ^ 1) * GSTAGE;
            uint32_t* sAhi = st;             uint32_t* sAlo = st + GTILE;
            uint32_t* sBhi = st + 2 * GTILE; uint32_t* sBlo = st + 3 * GTILE;
            const float* Ap = A + (kc + 1) * 32;
            const float* Wp = W + (kc + 1) * 32;
#pragma unroll
            for (int it = 0; it < 4; it++) {
                int row = it * 32 + lrow;
                float4 a4 = *(const float4*)(Ap + (size_t)(m0 + row) * K + lc4);
                float4 b4 = *(const float4*)(Wp + (size_t)(n0 + row) * K + lc4);
                uint32_t h0, l0, h1, l1;
                pack_bf16_pair(a4.x, a4.y, h0, l0); pack_bf16_pair(a4.z, a4.w, h1, l1);
                sAhi[row * GPAD + lp] = h0; sAhi[row * GPAD + lp + 1] = h1;
                sAlo[row * GPAD + lp] = l0; sAlo[row * GPAD + lp + 1] = l1;
                pack_bf16_pair(b4.x, b4.y, h0, l0); pack_bf16_pair(b4.z, b4.w, h1, l1);
                sBhi[row * GPAD + lp] = h0; sBhi[row * GPAD + lp + 1] = h1;
                sBlo[row * GPAD + lp] = l0; sBlo[row * GPAD + lp + 1] = l1;
            }
        }
        uint32_t* st = gsm + s * GSTAGE;
        uint32_t* sAhi = st;             uint32_t* sAlo = st + GTILE;
        uint32_t* sBhi = st + 2 * GTILE; uint32_t* sBlo = st + 3 * GTILE;
#pragma unroll
        for (int ks = 0; ks < 2; ks++) {
            int pc = ks * 8 + tg;
            uint32_t ahi[4][4], alo[4][4], bhi[4][2], blo[4][2];
#pragma unroll
            for (int mt = 0; mt < 4; mt++) {
                int base = (wm + mt * 16 + g) * GPAD + pc;
                ahi[mt][0] = sAhi[base];              alo[mt][0] = sAlo[base];
                ahi[mt][1] = sAhi[base + 8 * GPAD];   alo[mt][1] = sAlo[base + 8 * GPAD];
                ahi[mt][2] = sAhi[base + 4];          alo[mt][2] = sAlo[base + 4];
                ahi[mt][3] = sAhi[base + 8 * GPAD + 4]; alo[mt][3] = sAlo[base + 8 * GPAD + 4];
            }
#pragma unroll
            for (int nt = 0; nt < 4; nt++) {
                int base = (wn + nt * 8 + g) * GPAD + pc;
                bhi[nt][0] = sBhi[base]; bhi[nt][1] = sBhi[base + 4];
                blo[nt][0] = sBlo[base]; blo[nt][1] = sBlo[base + 4];
            }
#pragma unroll
            for (int mt = 0; mt < 4; mt++)
#pragma unroll
                for (int nt = 0; nt < 4; nt++) {
                    mma_bf16(acc[mt][nt], ahi[mt], bhi[nt]);
                    mma_bf16(acc[mt][nt], ahi[mt], blo[nt]);
                    mma_bf16(acc[mt][nt], alo[mt], bhi[nt]);
                }
        }
        __syncthreads();
    }

#pragma unroll
    for (int mt = 0; mt < 4; mt++) {
        int r0 = m0 + wm + mt * 16 + g;
#pragma unroll
        for (int nt = 0; nt < 4; nt++) {
            int col = n0 + wn + nt * 8 + 2 * tg;
            float bb0 = bias[col], bb1 = bias[col + 1];
            float2 v0, v1;
            v0.x = acc[mt][nt][0] + bb0; v0.y = acc[mt][nt][1] + bb1;
            v1.x = acc[mt][nt][2] + bb0; v1.y = acc[mt][nt][3] + bb1;
            *(float2*)(C + (size_t)r0 * Ncols + col) = v0;
            *(float2*)(C + (size_t)(r0 + 8) * Ncols + col) = v1;
        }
    }
}

// ---------------- fused attention on tensor cores ----------------
// grid (2, NHEAD, BATCH), 256 threads = 8 warps; warp w owns rows wm=16w..16w+15.
// K: smem bf16 hi/lo [key][16 u32-pairs] stride 20.  Q: same, 128 rows, scaled.
// V: smem f16 transposed Vt[dim][key-pair] stride 133 u32.
// QK: 3-term bf16 split mma (32 j-tiles x 2 k16 x 3).  PV: f16 mma (4 dt x 16 kt).
#define KSTR 20
#define VSTR 133
#define A_KHI 0
#define A_KLO 5120
#define A_QHI 10240
#define A_QLO 12800
#define A_VT  15360
#define A_TOT 19616    // u32
__global__ __launch_bounds__(256, 1)
void attn_kernel(const float* __restrict__ mask) {
    extern __shared__ uint32_t smu[];
    uint32_t* Khi = smu + A_KHI;
    uint32_t* Klo = smu + A_KLO;
    uint32_t* Qhi = smu + A_QHI;
    uint32_t* Qlo = smu + A_QLO;
    uint32_t* Vt  = smu + A_VT;
    __half*  Vth = (__half*)Vt;

    int tid = threadIdx.x, lane = tid & 31, w = tid >> 5;
    int r0 = blockIdx.x * 128, h = blockIdx.y, b = blockIdx.z;
    int g = lane >> 2, tg = lane & 3;

    // ---- load K, V (transpose V to f16), Q (scaled, split) ----
    {
        int key8 = tid >> 3, d4 = (tid & 7) * 4;
        const float scale = 0.17677669529663687f;   // 32^-0.5
#pragma unroll
        for (int it = 0; it < 8; it++) {
            int key = it * 32 + key8;
            const float* src = g_kv + (size_t)(b * NTOK + key) * (2 * DIMC) + h * HD + d4;
            float4 kx = *(const float4*)src;
            float4 vx = *(const float4*)(src + DIMC);
            uint32_t h0, l0, h1, l1;
            pack_bf16_pair(kx.x, kx.y, h0, l0);
            pack_bf16_pair(kx.z, kx.w, h1, l1);
            int kb = key * KSTR + (d4 >> 1);
            Khi[kb] = h0; Khi[kb + 1] = h1;
            Klo[kb] = l0; Klo[kb + 1] = l1;
            Vth[(d4 + 0) * (2 * VSTR) + key] = __float2half_rn(vx.x);
            Vth[(d4 + 1) * (2 * VSTR) + key] = __float2half_rn(vx.y);
            Vth[(d4 + 2) * (2 * VSTR) + key] = __float2half_rn(vx.z);
            Vth[(d4 + 3) * (2 * VSTR) + key] = __float2half_rn(vx.w);
        }
#pragma unroll
        for (int it = 0; it < 4; it++) {
            int row = it * 32 + key8;
            float4 qx = *(const float4*)(g_qh + (size_t)(b * NTOK + r0 + row) * DIMC + h * HD + d4);
            qx.x *= scale; qx.y *= scale; qx.z *= scale; qx.w *= scale;
            uint32_t h0, l0, h1, l1;
            pack_bf16_pair(qx.x, qx.y, h0, l0);
            pack_bf16_pair(qx.z, qx.w, h1, l1);
            int qb = row * KSTR + (d4 >> 1);
            Qhi[qb] = h0; Qhi[qb + 1] = h1;
            Qlo[qb] = l0; Qlo[qb + 1] = l1;
        }
    }
    __syncthreads();

    int wm = w * 16;

    // ---- Q fragments (2 k16 steps) ----
    uint32_t qh_[2][4], ql_[2][4];
#pragma unroll
    for (int ks = 0; ks < 2; ks++) {
        int ra = (wm + g) * KSTR + ks * 8 + tg;
        int rb = (wm + 8 + g) * KSTR + ks * 8 + tg;
        qh_[ks][0] = Qhi[ra]; qh_[ks][1] = Qhi[rb];
        qh_[ks][2] = Qhi[ra + 4]; qh_[ks][3] = Qhi[rb + 4];
        ql_[ks][0] = Qlo[ra]; ql_[ks][1] = Qlo[rb];
        ql_[ks][2] = Qlo[ra + 4]; ql_[ks][3] = Qlo[rb + 4];
    }

    // ---- QK^T scores ----
    float sc[32][4];
#pragma unroll
    for (int j = 0; j < 32; j++) { sc[j][0] = 0.f; sc[j][1] = 0.f; sc[j][2] = 0.f; sc[j][3] = 0.f; }
#pragma unroll
    for (int j = 0; j < 32; j++) {
#pragma unroll
        for (int ks = 0; ks < 2; ks++) {
            int kb = (j * 8 + g) * KSTR + ks * 8 + tg;
            uint32_t bh[2], bl[2];
            bh[0] = Khi[kb]; bh[1] = Khi[kb + 4];
            bl[0] = Klo[kb]; bl[1] = Klo[kb + 4];
            mma_bf16(sc[j], qh_[ks], bh);
            mma_bf16(sc[j], qh_[ks], bl);
            mma_bf16(sc[j], ql_[ks], bh);
        }
    }

    // ---- + rpb + mask (fragment rows wm+g, wm+8+g; cols j*8+2tg..+1) ----
    int R0 = r0 + wm + g;
    const float* rpbR = g_rpb + ((size_t)h * NTOK + R0) * NTOK;
    const float* mkR  = mask + ((size_t)(b & (NGROUP - 1)) * NTOK + R0) * NTOK;
#pragma unroll
    for (int j = 0; j < 32; j++) {
        int c = j * 8 + 2 * tg;
        float2 r0v = *(const float2*)(rpbR + c);
        float2 r1v = *(const float2*)(rpbR + 8 * NTOK + c);
        float2 m0v = *(const float2*)(mkR + c);
        float2 m1v = *(const float2*)(mkR + 8 * NTOK + c);
        sc[j][0] += r0v.x + m0v.x; sc[j][1] += r0v.y + m0v.y;
        sc[j][2] += r1v.x + m1v.x; sc[j][3] += r1v.y + m1v.y;
    }

    // ---- softmax (rows wm+g and wm+8+g; reduce over tg lanes via xor 1,2) ----
    float mx0 = -1e30f, mx1 = -1e30f;
#pragma unroll
    for (int j = 0; j < 32; j++) {
        mx0 = fmaxf(mx0, fmaxf(sc[j][0], sc[j][1]));
        mx1 = fmaxf(mx1, fmaxf(sc[j][2], sc[j][3]));
    }
    mx0 = fmaxf(mx0, __shfl_xor_sync(0xffffffffu, mx0, 1));
    mx0 = fmaxf(mx0, __shfl_xor_sync(0xffffffffu, mx0, 2));
    mx1 = fmaxf(mx1, __shfl_xor_sync(0xffffffffu, mx1, 1));
    mx1 = fmaxf(mx1, __shfl_xor_sync(0xffffffffu, mx1, 2));

    uint32_t pf[16][4];
    float sum0 = 0.f, sum1 = 0.f;
#pragma unroll
    for (int jj = 0; jj < 16; jj++) {
        __half2 e0 = h2exp(__floats2half2_rn(sc[2 * jj][0] - mx0, sc[2 * jj][1] - mx0));
        __half2 e1 = h2exp(__floats2half2_rn(sc[2 * jj][2] - mx1, sc[2 * jj][3] - mx1));
        __half2 e2 = h2exp(__floats2half2_rn(sc[2 * jj + 1][0] - mx0, sc[2 * jj + 1][1] - mx0));
        __half2 e3 = h2exp(__floats2half2_rn(sc[2 * jj + 1][2] - mx1, sc[2 * jj + 1][3] - mx1));
        pf[jj][0] = *(uint32_t*)&e0;
        pf[jj][1] = *(uint32_t*)&e1;
        pf[jj][2] = *(uint32_t*)&e2;
        pf[jj][3] = *(uint32_t*)&e3;
        float2 f0 = __half22float2(e0), f1 = __half22float2(e1);
        float2 f2 = __half22float2(e2), f3 = __half22float2(e3);
        sum0 += f0.x + f0.y + f2.x + f2.y;
        sum1 += f1.x + f1.y + f3.x + f3.y;
    }
    sum0 += __shfl_xor_sync(0xffffffffu, sum0, 1);
    sum0 += __shfl_xor_sync(0xffffffffu, sum0, 2);
    sum1 += __shfl_xor_sync(0xffffffffu, sum1, 1);
    sum1 += __shfl_xor_sync(0xffffffffu, sum1, 2);
    float inv0 = 1.0f / sum0, inv1 = 1.0f / sum1;

    // ---- P @ V (f16 mma; A = pf directly) ----
    float* xo0 = g_x + (size_t)(b * NTOK + R0) * DIMC + h * HD;
    float* xo1 = xo0 + 8 * DIMC;
#pragma unroll
    for (int dt = 0; dt < 4; dt++) {
        float ob[4] = {0.f, 0.f, 0.f, 0.f};
#pragma unroll
        for (int kt = 0; kt < 16; kt++) {
            int vb = (dt * 8 + g) * VSTR + kt * 8 + tg;
            uint32_t bv[2];
            bv[0] = Vt[vb]; bv[1] = Vt[vb + 4];
            mma_f16(ob, pf[kt], bv);
        }
        float2 o0, o1;
        o0.x = ob[0] * inv0; o0.y = ob[1] * inv0;
        o1.x = ob[2] * inv1; o1.y = ob[3] * inv1;
        *(float2*)(xo0 + dt * 8 + 2 * tg) = o0;
        *(float2*)(xo1 + dt * 8 + 2 * tg) = o1;
    }
}

// ---------------- launch ----------------
extern "C" void kernel_launch(void* const* d_in, const int* in_sizes, int n_in,
                              void* d_out, int out_size) {
    const float* q      = (const float*)d_in[0];
    const float* k      = (const float*)d_in[1];
    const float* mask   = (const float*)d_in[2];
    const float* q_w    = (const float*)d_in[3];
    const float* q_b    = (const float*)d_in[4];
    const float* kv_w   = (const float*)d_in[5];
    const float* kv_b   = (const float*)d_in[6];
    const float* proj_w = (const float*)d_in[7];
    const float* proj_b = (const float*)d_in[8];
    const float* pp_w   = (const float*)d_in[9];
    const float* pp_b   = (const float*)d_in[10];
    const float* ln1_g  = (const float*)d_in[11];
    const float* ln1_b  = (const float*)d_in[12];
    const float* l1_w   = (const float*)d_in[13];
    const float* l1_b   = (const float*)d_in[14];
    const float* ln2_g  = (const float*)d_in[15];
    const float* ln2_b  = (const float*)d_in[16];
    const float* l2_w   = (const float*)d_in[17];
    const float* l2_b   = (const float*)d_in[18];
    const float* ln3_g  = (const float*)d_in[19];
    const float* ln3_b  = (const float*)d_in[20];
    const float* l3_w   = (const float*)d_in[21];
    const float* l3_b   = (const float*)d_in[22];
    (void)in_sizes; (void)n_in; (void)out_size;

    float *qh, *kv, *x;
    cudaGetSymbolAddress((void**)&qh, g_qh);
    cudaGetSymbolAddress((void**)&kv, g_kv);
    cudaGetSymbolAddress((void**)&x,  g_x);

    int gsmem = 2 * GSTAGE * (int)sizeof(uint32_t);    // 81920
    int asmem = A_TOT * (int)sizeof(uint32_t);         // 78464
    static int attr_done = 0;
    if (!attr_done) {
        cudaFuncSetAttribute(gemm_bf16, cudaFuncAttributeMaxDynamicSharedMemorySize, gsmem);
        cudaFuncSetAttribute(attn_kernel, cudaFuncAttributeMaxDynamicSharedMemorySize, asmem);
        attr_done = 1;
    }

    pos_mlp_kernel<<<4, 256>>>(pp_w, pp_b, ln1_g, ln1_b, l1_w, l1_b,
                               ln2_g, ln2_b, l2_w, l2_b, ln3_g, ln3_b, l3_w, l3_b);
    rpb_fill_kernel<<<NHEAD * NTOK * NTOK / 256, 256>>>();

    const int M = BATCH * NTOK;   // 65536
    gemm_bf16<<<dim3(DIMC / 128, M / 128), 256, gsmem>>>(q, q_w, q_b, qh, M, DIMC, DIMC);
    gemm_bf16<<<dim3(2 * DIMC / 128, M / 128), 256, gsmem>>>(k, kv_w, kv_b, kv, M, 2 * DIMC, DIMC);

    attn_kernel<<<dim3(2, NHEAD, BATCH), 256, asmem>>>(mask);

    gemm_bf16<<<dim3(DIMC / 128, M / 128), 256, gsmem>>>(x, proj_w, proj_b, (float*)d_out, M, DIMC, DIMC);
}

// round 7
// speedup vs baseline: 3.9989x; 1.2143x over previous
#include <cuda_runtime.h>
#include <cuda_bf16.h>
#include <cuda_fp16.h>
#include <cstdint>
#include <cstddef>

// ---------------- problem constants ----------------
#define NHEAD 8
#define HD 32
#define NTOK 256
#define BATCH 256
#define DIMC 256
#define NGROUP 64
#define PD 16
#define LREL 961   // (2*16-1)^2

// ---------------- device scratch ----------------
__device__ float g_qh[BATCH * NTOK * DIMC];
__device__ float g_kv[BATCH * NTOK * 2 * DIMC];
__device__ float g_x [BATCH * NTOK * DIMC];
__device__ float g_pos[LREL * NHEAD];
__device__ float g_rpb[NHEAD * NTOK * NTOK];

// ---------------- mma helpers ----------------
__device__ __forceinline__ void pack_bf16_pair(float x, float y, uint32_t& hi, uint32_t& lo) {
    __nv_bfloat16 hx = __float2bfloat16_rn(x);
    __nv_bfloat16 hy = __float2bfloat16_rn(y);
    float rx = x - __bfloat162float(hx);
    float ry = y - __bfloat162float(hy);
    __nv_bfloat16 lx = __float2bfloat16_rn(rx);
    __nv_bfloat16 ly = __float2bfloat16_rn(ry);
    hi = ((uint32_t)__bfloat16_as_ushort(hy) << 16) | (uint32_t)__bfloat16_as_ushort(hx);
    lo = ((uint32_t)__bfloat16_as_ushort(ly) << 16) | (uint32_t)__bfloat16_as_ushort(lx);
}
__device__ __forceinline__ void mma_bf16(float* d, const uint32_t* a, const uint32_t* b) {
    asm volatile("mma.sync.aligned.m16n8k16.row.col.f32.bf16.bf16.f32 "
        "{%0,%1,%2,%3}, {%4,%5,%6,%7}, {%8,%9}, {%0,%1,%2,%3};"
        : "+f"(d[0]), "+f"(d[1]), "+f"(d[2]), "+f"(d[3])
        : "r"(a[0]), "r"(a[1]), "r"(a[2]), "r"(a[3]), "r"(b[0]), "r"(b[1]));
}
__device__ __forceinline__ void mma_f16(float* d, const uint32_t* a, const uint32_t* b) {
    asm volatile("mma.sync.aligned.m16n8k16.row.col.f32.f16.f16.f32 "
        "{%0,%1,%2,%3}, {%4,%5,%6,%7}, {%8,%9}, {%0,%1,%2,%3};"
        : "+f"(d[0]), "+f"(d[1]), "+f"(d[2]), "+f"(d[3])
        : "r"(a[0]), "r"(a[1]), "r"(a[2]), "r"(a[3]), "r"(b[0]), "r"(b[1]));
}

// ---------------- pos-bias MLP ----------------
__device__ __forceinline__ void ln16(float* x, const float* g, const float* b) {
    float m = 0.f;
#pragma unroll
    for (int i = 0; i < PD; i++) m += x[i];
    m *= (1.0f / PD);
    float v = 0.f;
#pragma unroll
    for (int i = 0; i < PD; i++) { float d = x[i] - m; v += d * d; }
    v *= (1.0f / PD);
    float inv = rsqrtf(v + 1e-5f);
#pragma unroll
    for (int i = 0; i < PD; i++) x[i] = (x[i] - m) * inv * g[i] + b[i];
}

__global__ void pos_mlp_kernel(const float* __restrict__ pp_w, const float* __restrict__ pp_b,
                               const float* __restrict__ ln1_g, const float* __restrict__ ln1_b,
                               const float* __restrict__ l1_w,  const float* __restrict__ l1_b,
                               const float* __restrict__ ln2_g, const float* __restrict__ ln2_b,
                               const float* __restrict__ l2_w,  const float* __restrict__ l2_b,
                               const float* __restrict__ ln3_g, const float* __restrict__ ln3_b,
                               const float* __restrict__ l3_w,  const float* __restrict__ l3_b) {
    int p = blockIdx.x * blockDim.x + threadIdx.x;
    if (p >= LREL) return;
    float b0 = (float)(p / 31 - 15);
    float b1 = (float)(p % 31 - 15);
    float x[PD], y[PD];
#pragma unroll
    for (int o = 0; o < PD; o++) x[o] = b0 * pp_w[o * 2 + 0] + b1 * pp_w[o * 2 + 1] + pp_b[o];
    ln16(x, ln1_g, ln1_b);
#pragma unroll
    for (int o = 0; o < PD; o++) {
        float s = l1_b[o];
#pragma unroll
        for (int i = 0; i < PD; i++) s += fmaxf(x[i], 0.f) * l1_w[o * PD + i];
        y[o] = s;
    }
#pragma unroll
    for (int o = 0; o < PD; o++) x[o] = y[o];
    ln16(x, ln2_g, ln2_b);
#pragma unroll
    for (int o = 0; o < PD; o++) {
        float s = l2_b[o];
#pragma unroll
        for (int i = 0; i < PD; i++) s += fmaxf(x[i], 0.f) * l2_w[o * PD + i];
        y[o] = s;
    }
#pragma unroll
    for (int o = 0; o < PD; o++) x[o] = y[o];
    ln16(x, ln3_g, ln3_b);
#pragma unroll
    for (int h = 0; h < NHEAD; h++) {
        float s = l3_b[h];
#pragma unroll
        for (int i = 0; i < PD; i++) s += fmaxf(x[i], 0.f) * l3_w[h * PD + i];
        g_pos[p * NHEAD + h] = s;
    }
}

__global__ void rpb_fill_kernel() {
    int i = blockIdx.x * 256 + threadIdx.x;
    int h = i >> 16;
    int rem = i & 65535;
    int n = rem >> 8;
    int m = rem & 255;
    int di = (n >> 4) - (m >> 4) + 15;
    int dj = (n & 15) - (m & 15) + 15;
    g_rpb[i] = g_pos[(di * 31 + dj) * NHEAD + h];
}

// ---------------- bf16-split mma.sync GEMM (swizzled, 2 CTAs/SM) ----------------
// Subtile [128][16 u32], physical col = c ^ (((row>>1)&3)<<2). Conflict-free
// fragment loads; 32KB/stage, 64KB/CTA total -> 2 CTAs per SM.
#define SWZ(r, c) (((r) << 4) + ((c) ^ ((((r) >> 1) & 3) << 2)))
#define GSW_TILE (128 * 16)
#define GSW_STAGE (4 * GSW_TILE)
__global__ __launch_bounds__(256, 2)
void gemm_bf16(const float* __restrict__ A, const float* __restrict__ W,
               const float* __restrict__ bias, float* __restrict__ C,
               int M, int Ncols, int K) {
    extern __shared__ uint32_t gsm[];
    int tid = threadIdx.x, lane = tid & 31, wid = tid >> 5;
    int m0 = blockIdx.y * 128, n0 = blockIdx.x * 128;
    int wm = (wid >> 2) * 64, wn = (wid & 3) * 32;
    int g = lane >> 2, tg = lane & 3;

    float acc[4][4][4];
#pragma unroll
    for (int a = 0; a < 4; a++)
#pragma unroll
        for (int bq = 0; bq < 4; bq++)
#pragma unroll
            for (int c = 0; c < 4; c++) acc[a][bq][c] = 0.f;

    int lrow = tid >> 3;
    int lc4 = (tid & 7) * 4;
    int lp = lc4 >> 1;

    {
        uint32_t* sAhi = gsm;                uint32_t* sAlo = gsm + GSW_TILE;
        uint32_t* sBhi = gsm + 2 * GSW_TILE; uint32_t* sBlo = gsm + 3 * GSW_TILE;
#pragma unroll
        for (int it = 0; it < 4; it++) {
            int row = it * 32 + lrow;
            float4 a4 = *(const float4*)(A + (size_t)(m0 + row) * K + lc4);
            float4 b4 = *(const float4*)(W + (size_t)(n0 + row) * K + lc4);
            uint32_t h0, l0, h1, l1;
            int p0 = SWZ(row, lp);
            pack_bf16_pair(a4.x, a4.y, h0, l0); pack_bf16_pair(a4.z, a4.w, h1, l1);
            sAhi[p0] = h0; sAhi[p0 + 1] = h1;
            sAlo[p0] = l0; sAlo[p0 + 1] = l1;
            pack_bf16_pair(b4.x, b4.y, h0, l0); pack_bf16_pair(b4.z, b4.w, h1, l1);
            sBhi[p0] = h0; sBhi[p0 + 1] = h1;
            sBlo[p0] = l0; sBlo[p0 + 1] = l1;
        }
    }
    __syncthreads();

    int nch = K >> 5;
    for (int kc = 0; kc < nch; kc++) {
        int s = kc & 1;
        if (kc + 1 < nch) {
            uint32_t* st = gsm + (s ^ 1) * GSW_STAGE;
            uint32_t* sAhi = st;                uint32_t* sAlo = st + GSW_TILE;
            uint32_t* sBhi = st + 2 * GSW_TILE; uint32_t* sBlo = st + 3 * GSW_TILE;
            const float* Ap = A + (kc + 1) * 32;
            const float* Wp = W + (kc + 1) * 32;
#pragma unroll
            for (int it = 0; it < 4; it++) {
                int row = it * 32 + lrow;
                float4 a4 = *(const float4*)(Ap + (size_t)(m0 + row) * K + lc4);
                float4 b4 = *(const float4*)(Wp + (size_t)(n0 + row) * K + lc4);
                uint32_t h0, l0, h1, l1;
                int p0 = SWZ(row, lp);
                pack_bf16_pair(a4.x, a4.y, h0, l0); pack_bf16_pair(a4.z, a4.w, h1, l1);
                sAhi[p0] = h0; sAhi[p0 + 1] = h1;
                sAlo[p0] = l0; sAlo[p0 + 1] = l1;
                pack_bf16_pair(b4.x, b4.y, h0, l0); pack_bf16_pair(b4.z, b4.w, h1, l1);
                sBhi[p0] = h0; sBhi[p0 + 1] = h1;
                sBlo[p0] = l0; sBlo[p0 + 1] = l1;
            }
        }
        uint32_t* st = gsm + s * GSW_STAGE;
        uint32_t* sAhi = st;                uint32_t* sAlo = st + GSW_TILE;
        uint32_t* sBhi = st + 2 * GSW_TILE; uint32_t* sBlo = st + 3 * GSW_TILE;
#pragma unroll
        for (int ks = 0; ks < 2; ks++) {
            int pc = ks * 8 + tg;
            uint32_t ahi[4][4], alo[4][4], bhi[4][2], blo[4][2];
#pragma unroll
            for (int mt = 0; mt < 4; mt++) {
                int ra = wm + mt * 16 + g;
                ahi[mt][0] = sAhi[SWZ(ra, pc)];         alo[mt][0] = sAlo[SWZ(ra, pc)];
                ahi[mt][1] = sAhi[SWZ(ra + 8, pc)];     alo[mt][1] = sAlo[SWZ(ra + 8, pc)];
                ahi[mt][2] = sAhi[SWZ(ra, pc + 4)];     alo[mt][2] = sAlo[SWZ(ra, pc + 4)];
                ahi[mt][3] = sAhi[SWZ(ra + 8, pc + 4)]; alo[mt][3] = sAlo[SWZ(ra + 8, pc + 4)];
            }
#pragma unroll
            for (int nt = 0; nt < 4; nt++) {
                int rb = wn + nt * 8 + g;
                bhi[nt][0] = sBhi[SWZ(rb, pc)]; bhi[nt][1] = sBhi[SWZ(rb, pc + 4)];
                blo[nt][0] = sBlo[SWZ(rb, pc)]; blo[nt][1] = sBlo[SWZ(rb, pc + 4)];
            }
#pragma unroll
            for (int mt = 0; mt < 4; mt++)
#pragma unroll
                for (int nt = 0; nt < 4; nt++) {
                    mma_bf16(acc[mt][nt], ahi[mt], bhi[nt]);
                    mma_bf16(acc[mt][nt], ahi[mt], blo[nt]);
                    mma_bf16(acc[mt][nt], alo[mt], bhi[nt]);
                }
        }
        __syncthreads();
    }

#pragma unroll
    for (int mt = 0; mt < 4; mt++) {
        int r0 = m0 + wm + mt * 16 + g;
#pragma unroll
        for (int nt = 0; nt < 4; nt++) {
            int col = n0 + wn + nt * 8 + 2 * tg;
            float bb0 = bias[col], bb1 = bias[col + 1];
            float2 v0, v1;
            v0.x = acc[mt][nt][0] + bb0; v0.y = acc[mt][nt][1] + bb1;
            v1.x = acc[mt][nt][2] + bb0; v1.y = acc[mt][nt][3] + bb1;
            *(float2*)(C + (size_t)r0 * Ncols + col) = v0;
            *(float2*)(C + (size_t)(r0 + 8) * Ncols + col) = v1;
        }
    }
}

// ---------------- fused attention on tensor cores (unchanged) ----------------
#define KSTR 20
#define VSTR 133
#define A_KHI 0
#define A_KLO 5120
#define A_QHI 10240
#define A_QLO 12800
#define A_VT  15360
#define A_TOT 19616    // u32
__global__ __launch_bounds__(256, 1)
void attn_kernel(const float* __restrict__ mask) {
    extern __shared__ uint32_t smu[];
    uint32_t* Khi = smu + A_KHI;
    uint32_t* Klo = smu + A_KLO;
    uint32_t* Qhi = smu + A_QHI;
    uint32_t* Qlo = smu + A_QLO;
    uint32_t* Vt  = smu + A_VT;
    __half*  Vth = (__half*)Vt;

    int tid = threadIdx.x, lane = tid & 31, w = tid >> 5;
    int r0 = blockIdx.x * 128, h = blockIdx.y, b = blockIdx.z;
    int g = lane >> 2, tg = lane & 3;

    {
        int key8 = tid >> 3, d4 = (tid & 7) * 4;
        const float scale = 0.17677669529663687f;   // 32^-0.5
#pragma unroll
        for (int it = 0; it < 8; it++) {
            int key = it * 32 + key8;
            const float* src = g_kv + (size_t)(b * NTOK + key) * (2 * DIMC) + h * HD + d4;
            float4 kx = *(const float4*)src;
            float4 vx = *(const float4*)(src + DIMC);
            uint32_t h0, l0, h1, l1;
            pack_bf16_pair(kx.x, kx.y, h0, l0);
            pack_bf16_pair(kx.z, kx.w, h1, l1);
            int kb = key * KSTR + (d4 >> 1);
            Khi[kb] = h0; Khi[kb + 1] = h1;
            Klo[kb] = l0; Klo[kb + 1] = l1;
            Vth[(d4 + 0) * (2 * VSTR) + key] = __float2half_rn(vx.x);
            Vth[(d4 + 1) * (2 * VSTR) + key] = __float2half_rn(vx.y);
            Vth[(d4 + 2) * (2 * VSTR) + key] = __float2half_rn(vx.z);
            Vth[(d4 + 3) * (2 * VSTR) + key] = __float2half_rn(vx.w);
        }
#pragma unroll
        for (int it = 0; it < 4; it++) {
            int row = it * 32 + key8;
            float4 qx = *(const float4*)(g_qh + (size_t)(b * NTOK + r0 + row) * DIMC + h * HD + d4);
            qx.x *= scale; qx.y *= scale; qx.z *= scale; qx.w *= scale;
            uint32_t h0, l0, h1, l1;
            pack_bf16_pair(qx.x, qx.y, h0, l0);
            pack_bf16_pair(qx.z, qx.w, h1, l1);
            int qb = row * KSTR + (d4 >> 1);
            Qhi[qb] = h0; Qhi[qb + 1] = h1;
            Qlo[qb] = l0; Qlo[qb + 1] = l1;
        }
    }
    __syncthreads();

    int wm = w * 16;

    uint32_t qh_[2][4], ql_[2][4];
#pragma unroll
    for (int ks = 0; ks < 2; ks++) {
        int ra = (wm + g) * KSTR + ks * 8 + tg;
        int rb = (wm + 8 + g) * KSTR + ks * 8 + tg;
        qh_[ks][0] = Qhi[ra]; qh_[ks][1] = Qhi[rb];
        qh_[ks][2] = Qhi[ra + 4]; qh_[ks][3] = Qhi[rb + 4];
        ql_[ks][0] = Qlo[ra]; ql_[ks][1] = Qlo[rb];
        ql_[ks][2] = Qlo[ra + 4]; ql_[ks][3] = Qlo[rb + 4];
    }

    float sc[32][4];
#pragma unroll
    for (int j = 0; j < 32; j++) { sc[j][0] = 0.f; sc[j][1] = 0.f; sc[j][2] = 0.f; sc[j][3] = 0.f; }
#pragma unroll
    for (int j = 0; j < 32; j++) {
#pragma unroll
        for (int ks = 0; ks < 2; ks++) {
            int kb = (j * 8 + g) * KSTR + ks * 8 + tg;
            uint32_t bh[2], bl[2];
            bh[0] = Khi[kb]; bh[1] = Khi[kb + 4];
            bl[0] = Klo[kb]; bl[1] = Klo[kb + 4];
            mma_bf16(sc[j], qh_[ks], bh);
            mma_bf16(sc[j], qh_[ks], bl);
            mma_bf16(sc[j], ql_[ks], bh);
        }
    }

    int R0 = r0 + wm + g;
    const float* rpbR = g_rpb + ((size_t)h * NTOK + R0) * NTOK;
    const float* mkR  = mask + ((size_t)(b & (NGROUP - 1)) * NTOK + R0) * NTOK;
#pragma unroll
    for (int j = 0; j < 32; j++) {
        int c = j * 8 + 2 * tg;
        float2 r0v = *(const float2*)(rpbR + c);
        float2 r1v = *(const float2*)(rpbR + 8 * NTOK + c);
        float2 m0v = *(const float2*)(mkR + c);
        float2 m1v = *(const float2*)(mkR + 8 * NTOK + c);
        sc[j][0] += r0v.x + m0v.x; sc[j][1] += r0v.y + m0v.y;
        sc[j][2] += r1v.x + m1v.x; sc[j][3] += r1v.y + m1v.y;
    }

    float mx0 = -1e30f, mx1 = -1e30f;
#pragma unroll
    for (int j = 0; j < 32; j++) {
        mx0 = fmaxf(mx0, fmaxf(sc[j][0], sc[j][1]));
        mx1 = fmaxf(mx1, fmaxf(sc[j][2], sc[j][3]));
    }
    mx0 = fmaxf(mx0, __shfl_xor_sync(0xffffffffu, mx0, 1));
    mx0 = fmaxf(mx0, __shfl_xor_sync(0xffffffffu, mx0, 2));
    mx1 = fmaxf(mx1, __shfl_xor_sync(0xffffffffu, mx1, 1));
    mx1 = fmaxf(mx1, __shfl_xor_sync(0xffffffffu, mx1, 2));

    uint32_t pf[16][4];
    float sum0 = 0.f, sum1 = 0.f;
#pragma unroll
    for (int jj = 0; jj < 16; jj++) {
        __half2 e0 = h2exp(__floats2half2_rn(sc[2 * jj][0] - mx0, sc[2 * jj][1] - mx0));
        __half2 e1 = h2exp(__floats2half2_rn(sc[2 * jj][2] - mx1, sc[2 * jj][3] - mx1));
        __half2 e2 = h2exp(__floats2half2_rn(sc[2 * jj + 1][0] - mx0, sc[2 * jj + 1][1] - mx0));
        __half2 e3 = h2exp(__floats2half2_rn(sc[2 * jj + 1][2] - mx1, sc[2 * jj + 1][3] - mx1));
        pf[jj][0] = *(uint32_t*)&e0;
        pf[jj][1] = *(uint32_t*)&e1;
        pf[jj][2] = *(uint32_t*)&e2;
        pf[jj][3] = *(uint32_t*)&e3;
        float2 f0 = __half22float2(e0), f1 = __half22float2(e1);
        float2 f2 = __half22float2(e2), f3 = __half22float2(e3);
        sum0 += f0.x + f0.y + f2.x + f2.y;
        sum1 += f1.x + f1.y + f3.x + f3.y;
    }
    sum0 += __shfl_xor_sync(0xffffffffu, sum0, 1);
    sum0 += __shfl_xor_sync(0xffffffffu, sum0, 2);
    sum1 += __shfl_xor_sync(0xffffffffu, sum1, 1);
    sum1 += __shfl_xor_sync(0xffffffffu, sum1, 2);
    float inv0 = 1.0f / sum0, inv1 = 1.0f / sum1;

    float* xo0 = g_x + (size_t)(b * NTOK + R0) * DIMC + h * HD;
    float* xo1 = xo0 + 8 * DIMC;
#pragma unroll
    for (int dt = 0; dt < 4; dt++) {
        float ob[4] = {0.f, 0.f, 0.f, 0.f};
#pragma unroll
        for (int kt = 0; kt < 16; kt++) {
            int vb = (dt * 8 + g) * VSTR + kt * 8 + tg;
            uint32_t bv[2];
            bv[0] = Vt[vb]; bv[1] = Vt[vb + 4];
            mma_f16(ob, pf[kt], bv);
        }
        float2 o0, o1;
        o0.x = ob[0] * inv0; o0.y = ob[1] * inv0;
        o1.x = ob[2] * inv1; o1.y = ob[3] * inv1;
        *(float2*)(xo0 + dt * 8 + 2 * tg) = o0;
        *(float2*)(xo1 + dt * 8 + 2 * tg) = o1;
    }
}

// ---------------- launch ----------------
extern "C" void kernel_launch(void* const* d_in, const int* in_sizes, int n_in,
                              void* d_out, int out_size) {
    const float* q      = (const float*)d_in[0];
    const float* k      = (const float*)d_in[1];
    const float* mask   = (const float*)d_in[2];
    const float* q_w    = (const float*)d_in[3];
    const float* q_b    = (const float*)d_in[4];
    const float* kv_w   = (const float*)d_in[5];
    const float* kv_b   = (const float*)d_in[6];
    const float* proj_w = (const float*)d_in[7];
    const float* proj_b = (const float*)d_in[8];
    const float* pp_w   = (const float*)d_in[9];
    const float* pp_b   = (const float*)d_in[10];
    const float* ln1_g  = (const float*)d_in[11];
    const float* ln1_b  = (const float*)d_in[12];
    const float* l1_w   = (const float*)d_in[13];
    const float* l1_b   = (const float*)d_in[14];
    const float* ln2_g  = (const float*)d_in[15];
    const float* ln2_b  = (const float*)d_in[16];
    const float* l2_w   = (const float*)d_in[17];
    const float* l2_b   = (const float*)d_in[18];
    const float* ln3_g  = (const float*)d_in[19];
    const float* ln3_b  = (const float*)d_in[20];
    const float* l3_w   = (const float*)d_in[21];
    const float* l3_b   = (const float*)d_in[22];
    (void)in_sizes; (void)n_in; (void)out_size;

    float *qh, *kv, *x;
    cudaGetSymbolAddress((void**)&qh, g_qh);
    cudaGetSymbolAddress((void**)&kv, g_kv);
    cudaGetSymbolAddress((void**)&x,  g_x);

    int gsmem = 2 * GSW_STAGE * (int)sizeof(uint32_t);   // 65536
    int asmem = A_TOT * (int)sizeof(uint32_t);           // 78464
    static int attr_done = 0;
    if (!attr_done) {
        cudaFuncSetAttribute(gemm_bf16, cudaFuncAttributeMaxDynamicSharedMemorySize, gsmem);
        cudaFuncSetAttribute(attn_kernel, cudaFuncAttributeMaxDynamicSharedMemorySize, asmem);
        attr_done = 1;
    }

    pos_mlp_kernel<<<4, 256>>>(pp_w, pp_b, ln1_g, ln1_b, l1_w, l1_b,
                               ln2_g, ln2_b, l2_w, l2_b, ln3_g, ln3_b, l3_w, l3_b);
    rpb_fill_kernel<<<NHEAD * NTOK * NTOK / 256, 256>>>();

    const int M = BATCH * NTOK;   // 65536
    gemm_bf16<<<dim3(DIMC / 128, M / 128), 256, gsmem>>>(q, q_w, q_b, qh, M, DIMC, DIMC);
    gemm_bf16<<<dim3(2 * DIMC / 128, M / 128), 256, gsmem>>>(k, kv_w, kv_b, kv, M, 2 * DIMC, DIMC);

    attn_kernel<<<dim3(2, NHEAD, BATCH), 256, asmem>>>(mask);

    gemm_bf16<<<dim3(DIMC / 128, M / 128), 256, gsmem>>>(x, proj_w, proj_b, (float*)d_out, M, DIMC, DIMC);
}

// round 9
// speedup vs baseline: 4.0028x; 1.0010x over previous
#include <cuda_runtime.h>
#include <cuda_bf16.h>
#include <cuda_fp16.h>
#include <cstdint>
#include <cstddef>

// ---------------- problem constants ----------------
#define NHEAD 8
#define HD 32
#define NTOK 256
#define BATCH 256
#define DIMC 256
#define NGROUP 64
#define PD 16
#define LREL 961
#define QSCALE 0.17677669529663687f

// ---------------- device scratch ----------------
__device__ float g_qh[BATCH * NTOK * DIMC];            // scaled Q (proj output)
__device__ float g_kv[BATCH * NTOK * 2 * DIMC];
__device__ float g_pos[LREL * NHEAD];
__device__ float g_rpb[NHEAD * NTOK * NTOK];
// packed bf16 hi/lo weights (pair-major: [row][k/2])
__device__ uint32_t g_qwhi[256 * 128],  g_qwlo[256 * 128];
__device__ uint32_t g_kvwhi[512 * 128], g_kvwlo[512 * 128];
__device__ uint32_t g_pwhi[256 * 128],  g_pwlo[256 * 128];
__device__ float g_qbs[256];
// attention output, packed bf16 hi/lo pairs: [row][dim/2]
__device__ uint32_t g_xhi[(size_t)BATCH * NTOK * 128];
__device__ uint32_t g_xlo[(size_t)BATCH * NTOK * 128];

// ---------------- helpers ----------------
__device__ __forceinline__ uint32_t smem_u32(const void* p) {
    uint32_t a;
    asm("{ .reg .u64 t; cvta.to.shared.u64 t, %1; cvt.u32.u64 %0, t; }" : "=r"(a) : "l"(p));
    return a;
}
__device__ __forceinline__ void cp16(uint32_t saddr, const void* g) {
    asm volatile("cp.async.cg.shared.global [%0], [%1], 16;" :: "r"(saddr), "l"(g) : "memory");
}
__device__ __forceinline__ void cp_commit() { asm volatile("cp.async.commit_group;" ::: "memory"); }
__device__ __forceinline__ void cp_wait0() { asm volatile("cp.async.wait_group 0;" ::: "memory"); }
__device__ __forceinline__ void cp_wait1() { asm volatile("cp.async.wait_group 1;" ::: "memory"); }

__device__ __forceinline__ void pack_bf16_pair(float x, float y, uint32_t& hi, uint32_t& lo) {
    __nv_bfloat16 hx = __float2bfloat16_rn(x);
    __nv_bfloat16 hy = __float2bfloat16_rn(y);
    float rx = x - __bfloat162float(hx);
    float ry = y - __bfloat162float(hy);
    __nv_bfloat16 lx = __float2bfloat16_rn(rx);
    __nv_bfloat16 ly = __float2bfloat16_rn(ry);
    hi = ((uint32_t)__bfloat16_as_ushort(hy) << 16) | (uint32_t)__bfloat16_as_ushort(hx);
    lo = ((uint32_t)__bfloat16_as_ushort(ly) << 16) | (uint32_t)__bfloat16_as_ushort(lx);
}
__device__ __forceinline__ void mma_bf16(float* d, const uint32_t* a, const uint32_t* b) {
    asm volatile("mma.sync.aligned.m16n8k16.row.col.f32.bf16.bf16.f32 "
        "{%0,%1,%2,%3}, {%4,%5,%6,%7}, {%8,%9}, {%0,%1,%2,%3};"
        : "+f"(d[0]), "+f"(d[1]), "+f"(d[2]), "+f"(d[3])
        : "r"(a[0]), "r"(a[1]), "r"(a[2]), "r"(a[3]), "r"(b[0]), "r"(b[1]));
}
__device__ __forceinline__ void mma_f16(float* d, const uint32_t* a, const uint32_t* b) {
    asm volatile("mma.sync.aligned.m16n8k16.row.col.f32.f16.f16.f32 "
        "{%0,%1,%2,%3}, {%4,%5,%6,%7}, {%8,%9}, {%0,%1,%2,%3};"
        : "+f"(d[0]), "+f"(d[1]), "+f"(d[2]), "+f"(d[3])
        : "r"(a[0]), "r"(a[1]), "r"(a[2]), "r"(a[3]), "r"(b[0]), "r"(b[1]));
}

// ---------------- weight pre-conversion ----------------
__global__ void conv_w_kernel(const float* __restrict__ qw, const float* __restrict__ kvw,
                              const float* __restrict__ pw, const float* __restrict__ qb) {
    int idx = blockIdx.x * 256 + threadIdx.x;   // 0..131071 (1024 rows x 128 pairs)
    int row = idx >> 7, p = idx & 127;
    const float* src;
    uint32_t *dh, *dl;
    float sc = 1.f;
    if (row < 256)      { src = qw + row * 256;          dh = g_qwhi + row * 128 + p;          dl = g_qwlo + row * 128 + p;          sc = QSCALE; }
    else if (row < 768) { int r = row - 256; src = kvw + r * 256; dh = g_kvwhi + r * 128 + p;  dl = g_kvwlo + r * 128 + p; }
    else                { int r = row - 768; src = pw + r * 256;  dh = g_pwhi + r * 128 + p;   dl = g_pwlo + r * 128 + p; }
    uint32_t hi, lo;
    pack_bf16_pair(src[2 * p] * sc, src[2 * p + 1] * sc, hi, lo);
    *dh = hi; *dl = lo;
    if (idx < 256) g_qbs[idx] = qb[idx] * QSCALE;
}

// ---------------- pos-bias MLP ----------------
__device__ __forceinline__ void ln16(float* x, const float* g, const float* b) {
    float m = 0.f;
#pragma unroll
    for (int i = 0; i < PD; i++) m += x[i];
    m *= (1.0f / PD);
    float v = 0.f;
#pragma unroll
    for (int i = 0; i < PD; i++) { float d = x[i] - m; v += d * d; }
    v *= (1.0f / PD);
    float inv = rsqrtf(v + 1e-5f);
#pragma unroll
    for (int i = 0; i < PD; i++) x[i] = (x[i] - m) * inv * g[i] + b[i];
}

__global__ void pos_mlp_kernel(const float* __restrict__ pp_w, const float* __restrict__ pp_b,
                               const float* __restrict__ ln1_g, const float* __restrict__ ln1_b,
                               const float* __restrict__ l1_w,  const float* __restrict__ l1_b,
                               const float* __restrict__ ln2_g, const float* __restrict__ ln2_b,
                               const float* __restrict__ l2_w,  const float* __restrict__ l2_b,
                               const float* __restrict__ ln3_g, const float* __restrict__ ln3_b,
                               const float* __restrict__ l3_w,  const float* __restrict__ l3_b) {
    int p = blockIdx.x * blockDim.x + threadIdx.x;
    if (p >= LREL) return;
    float b0 = (float)(p / 31 - 15);
    float b1 = (float)(p % 31 - 15);
    float x[PD], y[PD];
#pragma unroll
    for (int o = 0; o < PD; o++) x[o] = b0 * pp_w[o * 2 + 0] + b1 * pp_w[o * 2 + 1] + pp_b[o];
    ln16(x, ln1_g, ln1_b);
#pragma unroll
    for (int o = 0; o < PD; o++) {
        float s = l1_b[o];
#pragma unroll
        for (int i = 0; i < PD; i++) s += fmaxf(x[i], 0.f) * l1_w[o * PD + i];
        y[o] = s;
    }
#pragma unroll
    for (int o = 0; o < PD; o++) x[o] = y[o];
    ln16(x, ln2_g, ln2_b);
#pragma unroll
    for (int o = 0; o < PD; o++) {
        float s = l2_b[o];
#pragma unroll
        for (int i = 0; i < PD; i++) s += fmaxf(x[i], 0.f) * l2_w[o * PD + i];
        y[o] = s;
    }
#pragma unroll
    for (int o = 0; o < PD; o++) x[o] = y[o];
    ln16(x, ln3_g, ln3_b);
#pragma unroll
    for (int h = 0; h < NHEAD; h++) {
        float s = l3_b[h];
#pragma unroll
        for (int i = 0; i < PD; i++) s += fmaxf(x[i], 0.f) * l3_w[h * PD + i];
        g_pos[p * NHEAD + h] = s;
    }
}

__global__ void rpb_fill_kernel() {
    int i = blockIdx.x * 256 + threadIdx.x;
    int h = i >> 16;
    int rem = i & 65535;
    int n = rem >> 8;
    int m = rem & 255;
    int di = (n >> 4) - (m >> 4) + 15;
    int dj = (n & 15) - (m & 15) + 15;
    g_rpb[i] = g_pos[(di * 31 + dj) * NHEAD + h];
}

// ---------------- GEMM infrastructure ----------------
#define SWZ(r, c) (((r) << 4) + ((c) ^ ((((r) >> 1) & 3) << 2)))
#define GSW_TILE 2048
#define GSW_STAGE 8192

// async fill of a packed operand pair (hi at baseoff, lo at baseoff+GSW_TILE)
__device__ __forceinline__ void fill_packed_async(uint32_t sbase, int st, int baseoff, int tid,
                                                  const uint32_t* Whi, const uint32_t* Wlo,
                                                  int r0, int kc) {
#pragma unroll
    for (int i = 0; i < 2; i++) {
        int idx = tid * 2 + i;
        int row = idx >> 2, c4 = (idx & 3) << 2;
        uint32_t off = (uint32_t)((st * GSW_STAGE + baseoff + SWZ(row, c4)) * 4);
        size_t gidx = (size_t)(r0 + row) * 128 + kc * 16 + c4;
        cp16(sbase + off, Whi + gidx);
        cp16(sbase + off + GSW_TILE * 4, Wlo + gidx);
    }
}

__device__ __forceinline__ void gemm_compute(uint32_t* st, int wm, int wn, int g, int tg,
                                             float acc[4][4][4]) {
    uint32_t* sAhi = st;                uint32_t* sAlo = st + GSW_TILE;
    uint32_t* sBhi = st + 2 * GSW_TILE; uint32_t* sBlo = st + 3 * GSW_TILE;
#pragma unroll
    for (int ks = 0; ks < 2; ks++) {
        int pc = ks * 8 + tg;
        uint32_t ahi[4][4], alo[4][4], bhi[4][2], blo[4][2];
#pragma unroll
        for (int mt = 0; mt < 4; mt++) {
            int ra = wm + mt * 16 + g;
            ahi[mt][0] = sAhi[SWZ(ra, pc)];         alo[mt][0] = sAlo[SWZ(ra, pc)];
            ahi[mt][1] = sAhi[SWZ(ra + 8, pc)];     alo[mt][1] = sAlo[SWZ(ra + 8, pc)];
            ahi[mt][2] = sAhi[SWZ(ra, pc + 4)];     alo[mt][2] = sAlo[SWZ(ra, pc + 4)];
            ahi[mt][3] = sAhi[SWZ(ra + 8, pc + 4)]; alo[mt][3] = sAlo[SWZ(ra + 8, pc + 4)];
        }
#pragma unroll
        for (int nt = 0; nt < 4; nt++) {
            int rb = wn + nt * 8 + g;
            bhi[nt][0] = sBhi[SWZ(rb, pc)]; bhi[nt][1] = sBhi[SWZ(rb, pc + 4)];
            blo[nt][0] = sBlo[SWZ(rb, pc)]; blo[nt][1] = sBlo[SWZ(rb, pc + 4)];
        }
#pragma unroll
        for (int mt = 0; mt < 4; mt++)
#pragma unroll
            for (int nt = 0; nt < 4; nt++) {
                mma_bf16(acc[mt][nt], ahi[mt], bhi[nt]);
                mma_bf16(acc[mt][nt], ahi[mt], blo[nt]);
                mma_bf16(acc[mt][nt], alo[mt], bhi[nt]);
            }
    }
}

// ---------------- merged Q + KV projection GEMM ----------------
// grid (6, 512): bx<2 -> Q (N=256), bx>=2 -> KV (N=512). A fp32 (converted in-kernel),
// B packed via cp.async.
__global__ __launch_bounds__(256, 2)
void gemm_qkv(const float* __restrict__ q, const float* __restrict__ kfeat,
              const float* __restrict__ kv_b) {
    extern __shared__ uint32_t gsm[];
    uint32_t sbase = smem_u32(gsm);
    int tid = threadIdx.x, lane = tid & 31, wid = tid >> 5;
    int bx = blockIdx.x, m0 = blockIdx.y * 128;
    const float* A; const uint32_t *Whi, *Wlo; float* C; const float* bias; int Ncols, n0;
    if (bx < 2) { A = q;     Whi = g_qwhi;  Wlo = g_qwlo;  C = g_qh; bias = g_qbs; Ncols = 256; n0 = bx * 128; }
    else        { A = kfeat; Whi = g_kvwhi; Wlo = g_kvwlo; C = g_kv; bias = kv_b;  Ncols = 512; n0 = (bx - 2) * 128; }

    int wm = (wid >> 2) * 64, wn = (wid & 3) * 32;
    int g = lane >> 2, tg = lane & 3;
    int lrow = tid >> 3, lc4 = (tid & 7) * 4, lp = lc4 >> 1;

    float acc[4][4][4];
#pragma unroll
    for (int a = 0; a < 4; a++)
#pragma unroll
        for (int bq = 0; bq < 4; bq++)
#pragma unroll
            for (int c = 0; c < 4; c++) acc[a][bq][c] = 0.f;

    // prologue: stage 0
    {
        uint32_t* st0 = gsm;
#pragma unroll
        for (int it = 0; it < 4; it++) {
            int row = it * 32 + lrow;
            float4 a4 = *(const float4*)(A + (size_t)(m0 + row) * 256 + lc4);
            uint32_t h0, l0, h1, l1;
            pack_bf16_pair(a4.x, a4.y, h0, l0); pack_bf16_pair(a4.z, a4.w, h1, l1);
            int p0 = SWZ(row, lp);
            st0[p0] = h0; st0[p0 + 1] = h1;
            st0[GSW_TILE + p0] = l0; st0[GSW_TILE + p0 + 1] = l1;
        }
        fill_packed_async(sbase, 0, 2 * GSW_TILE, tid, Whi, Wlo, n0, 0);
        cp_commit();
    }

    for (int kc = 0; kc < 8; kc++) {
        int s = kc & 1;
        bool pre = (kc + 1 < 8);
        float4 a4[4];
        if (pre) {
#pragma unroll
            for (int it = 0; it < 4; it++) {
                int row = it * 32 + lrow;
                a4[it] = *(const float4*)(A + (size_t)(m0 + row) * 256 + (kc + 1) * 32 + lc4);
            }
            fill_packed_async(sbase, s ^ 1, 2 * GSW_TILE, tid, Whi, Wlo, n0, kc + 1);
            cp_commit();
            cp_wait1();
        } else {
            cp_wait0();
        }
        __syncthreads();
        gemm_compute(gsm + s * GSW_STAGE, wm, wn, g, tg, acc);
        if (pre) {
            uint32_t* stn = gsm + (s ^ 1) * GSW_STAGE;
#pragma unroll
            for (int it = 0; it < 4; it++) {
                int row = it * 32 + lrow;
                uint32_t h0, l0, h1, l1;
                pack_bf16_pair(a4[it].x, a4[it].y, h0, l0); pack_bf16_pair(a4[it].z, a4[it].w, h1, l1);
                int p0 = SWZ(row, lp);
                stn[p0] = h0; stn[p0 + 1] = h1;
                stn[GSW_TILE + p0] = l0; stn[GSW_TILE + p0 + 1] = l1;
            }
        }
        __syncthreads();
    }

#pragma unroll
    for (int mt = 0; mt < 4; mt++) {
        int r0 = m0 + wm + mt * 16 + g;
#pragma unroll
        for (int nt = 0; nt < 4; nt++) {
            int col = n0 + wn + nt * 8 + 2 * tg;
            float bb0 = bias[col], bb1 = bias[col + 1];
            float2 v0, v1;
            v0.x = acc[mt][nt][0] + bb0; v0.y = acc[mt][nt][1] + bb1;
            v1.x = acc[mt][nt][2] + bb0; v1.y = acc[mt][nt][3] + bb1;
            *(float2*)(C + (size_t)r0 * Ncols + col) = v0;
            *(float2*)(C + (size_t)(r0 + 8) * Ncols + col) = v1;
        }
    }
}

// ---------------- output projection GEMM: A packed (from attention), B packed ----------------
__global__ __launch_bounds__(256, 2)
void gemm_proj(const float* __restrict__ proj_b, float* __restrict__ out) {
    extern __shared__ uint32_t gsm[];
    uint32_t sbase = smem_u32(gsm);
    int tid = threadIdx.x, lane = tid & 31, wid = tid >> 5;
    int m0 = blockIdx.y * 128, n0 = blockIdx.x * 128;
    int wm = (wid >> 2) * 64, wn = (wid & 3) * 32;
    int g = lane >> 2, tg = lane & 3;

    float acc[4][4][4];
#pragma unroll
    for (int a = 0; a < 4; a++)
#pragma unroll
        for (int bq = 0; bq < 4; bq++)
#pragma unroll
            for (int c = 0; c < 4; c++) acc[a][bq][c] = 0.f;

    fill_packed_async(sbase, 0, 0, tid, g_xhi, g_xlo, m0, 0);
    fill_packed_async(sbase, 0, 2 * GSW_TILE, tid, g_pwhi, g_pwlo, n0, 0);
    cp_commit();

    for (int kc = 0; kc < 8; kc++) {
        int s = kc & 1;
        bool pre = (kc + 1 < 8);
        if (pre) {
            fill_packed_async(sbase, s ^ 1, 0, tid, g_xhi, g_xlo, m0, kc + 1);
            fill_packed_async(sbase, s ^ 1, 2 * GSW_TILE, tid, g_pwhi, g_pwlo, n0, kc + 1);
            cp_commit();
            cp_wait1();
        } else {
            cp_wait0();
        }
        __syncthreads();
        gemm_compute(gsm + s * GSW_STAGE, wm, wn, g, tg, acc);
        __syncthreads();
    }

#pragma unroll
    for (int mt = 0; mt < 4; mt++) {
        int r0 = m0 + wm + mt * 16 + g;
#pragma unroll
        for (int nt = 0; nt < 4; nt++) {
            int col = n0 + wn + nt * 8 + 2 * tg;
            float bb0 = proj_b[col], bb1 = proj_b[col + 1];
            float2 v0, v1;
            v0.x = acc[mt][nt][0] + bb0; v0.y = acc[mt][nt][1] + bb1;
            v1.x = acc[mt][nt][2] + bb0; v1.y = acc[mt][nt][3] + bb1;
            *(float2*)(out + (size_t)r0 * 256 + col) = v0;
            *(float2*)(out + (size_t)(r0 + 8) * 256 + col) = v1;
        }
    }
}

// ---------------- fused attention on tensor cores ----------------
#define KSTR 20
#define VSTR 133
#define A_KHI 0
#define A_KLO 5120
#define A_QHI 10240
#define A_QLO 12800
#define A_VT  15360
#define A_TOT 19616
__global__ __launch_bounds__(256, 1)
void attn_kernel(const float* __restrict__ mask) {
    extern __shared__ uint32_t smu[];
    uint32_t* Khi = smu + A_KHI;
    uint32_t* Klo = smu + A_KLO;
    uint32_t* Qhi = smu + A_QHI;
    uint32_t* Qlo = smu + A_QLO;
    uint32_t* Vt  = smu + A_VT;
    __half*  Vth = (__half*)Vt;

    int tid = threadIdx.x, lane = tid & 31, w = tid >> 5;
    int r0 = blockIdx.x * 128, h = blockIdx.y, b = blockIdx.z;
    int g = lane >> 2, tg = lane & 3;

    {
        int key8 = tid >> 3, d4 = (tid & 7) * 4;
#pragma unroll
        for (int it = 0; it < 8; it++) {
            int key = it * 32 + key8;
            const float* src = g_kv + (size_t)(b * NTOK + key) * (2 * DIMC) + h * HD + d4;
            float4 kx = *(const float4*)src;
            float4 vx = *(const float4*)(src + DIMC);
            uint32_t h0, l0, h1, l1;
            pack_bf16_pair(kx.x, kx.y, h0, l0);
            pack_bf16_pair(kx.z, kx.w, h1, l1);
            int kb = key * KSTR + (d4 >> 1);
            Khi[kb] = h0; Khi[kb + 1] = h1;
            Klo[kb] = l0; Klo[kb + 1] = l1;
            Vth[(d4 + 0) * (2 * VSTR) + key] = __float2half_rn(vx.x);
            Vth[(d4 + 1) * (2 * VSTR) + key] = __float2half_rn(vx.y);
            Vth[(d4 + 2) * (2 * VSTR) + key] = __float2half_rn(vx.z);
            Vth[(d4 + 3) * (2 * VSTR) + key] = __float2half_rn(vx.w);
        }
#pragma unroll
        for (int it = 0; it < 4; it++) {
            int row = it * 32 + key8;
            float4 qx = *(const float4*)(g_qh + (size_t)(b * NTOK + r0 + row) * DIMC + h * HD + d4);
            uint32_t h0, l0, h1, l1;
            pack_bf16_pair(qx.x, qx.y, h0, l0);
            pack_bf16_pair(qx.z, qx.w, h1, l1);
            int qb = row * KSTR + (d4 >> 1);
            Qhi[qb] = h0; Qhi[qb + 1] = h1;
            Qlo[qb] = l0; Qlo[qb + 1] = l1;
        }
    }
    __syncthreads();

    int wm = w * 16;

    uint32_t qh_[2][4], ql_[2][4];
#pragma unroll
    for (int ks = 0; ks < 2; ks++) {
        int ra = (wm + g) * KSTR + ks * 8 + tg;
        int rb = (wm + 8 + g) * KSTR + ks * 8 + tg;
        qh_[ks][0] = Qhi[ra]; qh_[ks][1] = Qhi[rb];
        qh_[ks][2] = Qhi[ra + 4]; qh_[ks][3] = Qhi[rb + 4];
        ql_[ks][0] = Qlo[ra]; ql_[ks][1] = Qlo[rb];
        ql_[ks][2] = Qlo[ra + 4]; ql_[ks][3] = Qlo[rb + 4];
    }

    float sc[32][4];
#pragma unroll
    for (int j = 0; j < 32; j++) { sc[j][0] = 0.f; sc[j][1] = 0.f; sc[j][2] = 0.f; sc[j][3] = 0.f; }
#pragma unroll
    for (int j = 0; j < 32; j++) {
#pragma unroll
        for (int ks = 0; ks < 2; ks++) {
            int kb = (j * 8 + g) * KSTR + ks * 8 + tg;
            uint32_t bh[2], bl[2];
            bh[0] = Khi[kb]; bh[1] = Khi[kb + 4];
            bl[0] = Klo[kb]; bl[1] = Klo[kb + 4];
            mma_bf16(sc[j], qh_[ks], bh);
            mma_bf16(sc[j], qh_[ks], bl);
            mma_bf16(sc[j], ql_[ks], bh);
        }
    }

    int R0 = r0 + wm + g;
    const float* rpbR = g_rpb + ((size_t)h * NTOK + R0) * NTOK;
    const float* mkR  = mask + ((size_t)(b & (NGROUP - 1)) * NTOK + R0) * NTOK;
#pragma unroll
    for (int j = 0; j < 32; j++) {
        int c = j * 8 + 2 * tg;
        float2 r0v = *(const float2*)(rpbR + c);
        float2 r1v = *(const float2*)(rpbR + 8 * NTOK + c);
        float2 m0v = *(const float2*)(mkR + c);
        float2 m1v = *(const float2*)(mkR + 8 * NTOK + c);
        sc[j][0] += r0v.x + m0v.x; sc[j][1] += r0v.y + m0v.y;
        sc[j][2] += r1v.x + m1v.x; sc[j][3] += r1v.y + m1v.y;
    }

    float mx0 = -1e30f, mx1 = -1e30f;
#pragma unroll
    for (int j = 0; j < 32; j++) {
        mx0 = fmaxf(mx0, fmaxf(sc[j][0], sc[j][1]));
        mx1 = fmaxf(mx1, fmaxf(sc[j][2], sc[j][3]));
    }
    mx0 = fmaxf(mx0, __shfl_xor_sync(0xffffffffu, mx0, 1));
    mx0 = fmaxf(mx0, __shfl_xor_sync(0xffffffffu, mx0, 2));
    mx1 = fmaxf(mx1, __shfl_xor_sync(0xffffffffu, mx1, 1));
    mx1 = fmaxf(mx1, __shfl_xor_sync(0xffffffffu, mx1, 2));

    uint32_t pf[16][4];
    float sum0 = 0.f, sum1 = 0.f;
#pragma unroll
    for (int jj = 0; jj < 16; jj++) {
        __half2 e0 = h2exp(__floats2half2_rn(sc[2 * jj][0] - mx0, sc[2 * jj][1] - mx0));
        __half2 e1 = h2exp(__floats2half2_rn(sc[2 * jj][2] - mx1, sc[2 * jj][3] - mx1));
        __half2 e2 = h2exp(__floats2half2_rn(sc[2 * jj + 1][0] - mx0, sc[2 * jj + 1][1] - mx0));
        __half2 e3 = h2exp(__floats2half2_rn(sc[2 * jj + 1][2] - mx1, sc[2 * jj + 1][3] - mx1));
        pf[jj][0] = *(uint32_t*)&e0;
        pf[jj][1] = *(uint32_t*)&e1;
        pf[jj][2] = *(uint32_t*)&e2;
        pf[jj][3] = *(uint32_t*)&e3;
        float2 f0 = __half22float2(e0), f1 = __half22float2(e1);
        float2 f2 = __half22float2(e2), f3 = __half22float2(e3);
        sum0 += f0.x + f0.y + f2.x + f2.y;
        sum1 += f1.x + f1.y + f3.x + f3.y;
    }
    sum0 += __shfl_xor_sync(0xffffffffu, sum0, 1);
    sum0 += __shfl_xor_sync(0xffffffffu, sum0, 2);
    sum1 += __shfl_xor_sync(0xffffffffu, sum1, 1);
    sum1 += __shfl_xor_sync(0xffffffffu, sum1, 2);
    float inv0 = 1.0f / sum0, inv1 = 1.0f / sum1;

    size_t ro0 = (size_t)(b * NTOK + R0) * 128;
    size_t ro1 = ro0 + 8 * 128;
#pragma unroll
    for (int dt = 0; dt < 4; dt++) {
        float ob[4] = {0.f, 0.f, 0.f, 0.f};
#pragma unroll
        for (int kt = 0; kt < 16; kt++) {
            int vb = (dt * 8 + g) * VSTR + kt * 8 + tg;
            uint32_t bv[2];
            bv[0] = Vt[vb]; bv[1] = Vt[vb + 4];
            mma_f16(ob, pf[kt], bv);
        }
        int pc = h * 16 + dt * 4 + tg;
        uint32_t hi0, lo0, hi1, lo1;
        pack_bf16_pair(ob[0] * inv0, ob[1] * inv0, hi0, lo0);
        pack_bf16_pair(ob[2] * inv1, ob[3] * inv1, hi1, lo1);
        g_xhi[ro0 + pc] = hi0; g_xlo[ro0 + pc] = lo0;
        g_xhi[ro1 + pc] = hi1; g_xlo[ro1 + pc] = lo1;
    }
}

// ---------------- launch ----------------
extern "C" void kernel_launch(void* const* d_in, const int* in_sizes, int n_in,
                              void* d_out, int out_size) {
    const float* q      = (const float*)d_in[0];
    const float* k      = (const float*)d_in[1];
    const float* mask   = (const float*)d_in[2];
    const float* q_w    = (const float*)d_in[3];
    const float* q_b    = (const float*)d_in[4];
    const float* kv_w   = (const float*)d_in[5];
    const float* kv_b   = (const float*)d_in[6];
    const float* proj_w = (const float*)d_in[7];
    const float* proj_b = (const float*)d_in[8];
    const float* pp_w   = (const float*)d_in[9];
    const float* pp_b   = (const float*)d_in[10];
    const float* ln1_g  = (const float*)d_in[11];
    const float* ln1_b  = (const float*)d_in[12];
    const float* l1_w   = (const float*)d_in[13];
    const float* l1_b   = (const float*)d_in[14];
    const float* ln2_g  = (const float*)d_in[15];
    const float* ln2_b  = (const float*)d_in[16];
    const float* l2_w   = (const float*)d_in[17];
    const float* l2_b   = (const float*)d_in[18];
    const float* ln3_g  = (const float*)d_in[19];
    const float* ln3_b  = (const float*)d_in[20];
    const float* l3_w   = (const float*)d_in[21];
    const float* l3_b   = (const float*)d_in[22];
    (void)in_sizes; (void)n_in; (void)out_size;

    int gsmem = 2 * GSW_STAGE * (int)sizeof(uint32_t);   // 65536
    int asmem = A_TOT * (int)sizeof(uint32_t);           // 78464
    static int attr_done = 0;
    if (!attr_done) {
        cudaFuncSetAttribute(gemm_qkv, cudaFuncAttributeMaxDynamicSharedMemorySize, gsmem);
        cudaFuncSetAttribute(gemm_proj, cudaFuncAttributeMaxDynamicSharedMemorySize, gsmem);
        cudaFuncSetAttribute(attn_kernel, cudaFuncAttributeMaxDynamicSharedMemorySize, asmem);
        attr_done = 1;
    }

    conv_w_kernel<<<512, 256>>>(q_w, kv_w, proj_w, q_b);
    pos_mlp_kernel<<<4, 256>>>(pp_w, pp_b, ln1_g, ln1_b, l1_w, l1_b,
                               ln2_g, ln2_b, l2_w, l2_b, ln3_g, ln3_b, l3_w, l3_b);
    rpb_fill_kernel<<<NHEAD * NTOK * NTOK / 256, 256>>>();

    gemm_qkv<<<dim3(6, 512), 256, gsmem>>>(q, k, kv_b);
    attn_kernel<<<dim3(2, NHEAD, BATCH), 256, asmem>>>(mask);
    gemm_proj<<<dim3(2, 512), 256, gsmem>>>(proj_b, (float*)d_out);
}